// round 2
// baseline (speedup 1.0000x reference)
#include <cuda_runtime.h>
#include <math.h>

// Problem constants
#define NB 100000
#define NC 10000
#define EB 400000
#define EC 80000
#define ECT (EC + NC)   // community edges + self loops = 90000
#define EBT (EB + NB)   // building edges + self loops = 500000

// ---------------------------------------------------------------------------
// Scratch: one big device global (allocation-free rule)
// ---------------------------------------------------------------------------
constexpr long long O_CXL  = 0;
constexpr long long O_CXR  = O_CXL  + (long long)NC * 512;
constexpr long long O_CH1  = O_CXR  + (long long)NC * 512;
constexpr long long O_CAGG = O_CH1  + (long long)NC * 512;
constexpr long long O_CXL2 = O_CAGG + (long long)NC * 512;
constexpr long long O_CXR2 = O_CXL2 + (long long)NC * 128;
constexpr long long O_CH2  = O_CXR2 + (long long)NC * 128;
constexpr long long O_CEP  = O_CH2  + (long long)NC * 128;
constexpr long long O_CMAX = O_CEP  + (long long)ECT * 8;
constexpr long long O_CSUM = O_CMAX + (long long)NC * 8;
constexpr long long O_COMB = O_CSUM + (long long)NC * 8;
constexpr long long O_FAH  = O_COMB + (long long)NB * 192;
constexpr long long O_WM   = O_FAH  + (long long)NB * 1024;
constexpr long long O_BXL  = O_WM   + (long long)NB * 2;
constexpr long long O_BXR  = O_BXL  + (long long)NB * 512;
constexpr long long O_BAGG = O_BXR  + (long long)NB * 512;
constexpr long long O_BH1  = O_BAGG + (long long)NB * 512;
constexpr long long O_BH2  = O_BH1  + (long long)NB * 512;
constexpr long long O_BEP  = O_BH2  + (long long)NB * 128;
constexpr long long O_BMAX = O_BEP  + (long long)EBT * 8;
constexpr long long O_BSUM = O_BMAX + (long long)NB * 8;
constexpr long long O_XL3  = O_BSUM + (long long)NB * 8;
constexpr long long O_XR3  = O_XL3  + (long long)NB * 2;
constexpr long long O_AGG3 = O_XR3  + (long long)NB * 2;
constexpr long long SCRATCH_TOTAL = O_AGG3 + (long long)NB * 2;

__device__ float g_scratch[SCRATCH_TOTAL];

// ---------------------------------------------------------------------------
// Helpers
// ---------------------------------------------------------------------------
__device__ __forceinline__ void atomicMaxF(float* addr, float v) {
    if (v >= 0.0f)
        atomicMax((int*)addr, __float_as_int(v));
    else
        atomicMin((unsigned int*)addr, __float_as_uint(v));
}

__global__ void fillk(float* __restrict__ x, float v, long long n) {
    long long i = (long long)blockIdx.x * blockDim.x + threadIdx.x;
    if (i < n) x[i] = v;
}

// ---------------------------------------------------------------------------
// Tiled SGEMM: C[N,M] = A[N,K] @ B[K,M] (+bias, optional relu), ldc for C.
// K must be a multiple of 16 (all layers satisfy this).
// ---------------------------------------------------------------------------
#define BM 64
#define BN 64
#define BK 16

__global__ void sgemm_bias_relu(const float* __restrict__ A, const float* __restrict__ B,
                                float* __restrict__ C, const float* __restrict__ bias,
                                int N, int K, int M, int ldc, int relu)
{
    __shared__ float As[BK][BM];
    __shared__ float Bs[BK][BN];
    int tid = threadIdx.x;            // 256 threads
    int tx = tid % 16, ty = tid / 16;
    int rowBase = blockIdx.y * BM;
    int colBase = blockIdx.x * BN;
    float acc[4][4] = {};

    for (int k0 = 0; k0 < K; k0 += BK) {
        #pragma unroll
        for (int i = 0; i < 4; i++) {
            int idx = tid + i * 256;         // 0..1023
            int m = idx / BK, kk = idx % BK;
            int gr = rowBase + m;
            As[kk][m] = (gr < N) ? A[(long long)gr * K + k0 + kk] : 0.0f;
        }
        #pragma unroll
        for (int i = 0; i < 4; i++) {
            int idx = tid + i * 256;
            int kk = idx / BN, n = idx % BN;
            int gc = colBase + n;
            Bs[kk][n] = (gc < M) ? B[(long long)(k0 + kk) * M + gc] : 0.0f;
        }
        __syncthreads();
        #pragma unroll
        for (int kk = 0; kk < BK; kk++) {
            float a[4], b[4];
            #pragma unroll
            for (int i = 0; i < 4; i++) a[i] = As[kk][ty * 4 + i];
            #pragma unroll
            for (int j = 0; j < 4; j++) b[j] = Bs[kk][tx * 4 + j];
            #pragma unroll
            for (int i = 0; i < 4; i++)
                #pragma unroll
                for (int j = 0; j < 4; j++)
                    acc[i][j] += a[i] * b[j];
        }
        __syncthreads();
    }
    #pragma unroll
    for (int i = 0; i < 4; i++) {
        int r = rowBase + ty * 4 + i;
        if (r >= N) continue;
        #pragma unroll
        for (int j = 0; j < 4; j++) {
            int c = colBase + tx * 4 + j;
            if (c >= M) continue;
            float v = acc[i][j];
            if (bias) v += bias[c];
            if (relu) v = fmaxf(v, 0.0f);
            C[(long long)r * ldc + c] = v;
        }
    }
}

// ---------------------------------------------------------------------------
// GATv2 edge kernels. Edge list: ei[0..E_real) = src row, ei[E_real..2E) = dst.
// Edges e >= E_real are self loops: src = dst = e - E_real.
// ---------------------------------------------------------------------------
__global__ void edge_logits(const int* __restrict__ ei, int E_real, int E_tot,
                            const float* __restrict__ xl, const float* __restrict__ xr,
                            const float* __restrict__ att, float* __restrict__ p,
                            float* __restrict__ segmax, int H, int D)
{
    long long w = ((long long)blockIdx.x * blockDim.x + threadIdx.x) >> 5;
    int lane = threadIdx.x & 31;
    if (w >= (long long)E_tot * H) return;
    int e = (int)(w / H), h = (int)(w % H);
    int src, dst;
    if (e < E_real) { src = ei[e]; dst = ei[E_real + e]; }
    else            { src = dst = e - E_real; }
    const float* pl = xl + (long long)src * H * D + h * D;
    const float* pr = xr + (long long)dst * H * D + h * D;
    const float* pa = att + h * D;
    float s = 0.0f;
    for (int d = lane; d < D; d += 32) {
        float v = pl[d] + pr[d];
        v = v > 0.0f ? v : 0.2f * v;        // leaky_relu 0.2
        s += v * pa[d];
    }
    #pragma unroll
    for (int o = 16; o; o >>= 1) s += __shfl_down_sync(0xffffffffu, s, o);
    if (lane == 0) {
        p[(long long)e * H + h] = s;
        atomicMaxF(&segmax[(long long)dst * H + h], s);
    }
}

__global__ void edge_exp(const int* __restrict__ ei, int E_real, int E_tot,
                         float* __restrict__ p, const float* __restrict__ segmax,
                         float* __restrict__ segsum, int H)
{
    long long i = (long long)blockIdx.x * blockDim.x + threadIdx.x;
    if (i >= (long long)E_tot * H) return;
    int e = (int)(i / H), h = (int)(i % H);
    int dst = (e < E_real) ? ei[E_real + e] : e - E_real;
    float v = expf(p[i] - segmax[(long long)dst * H + h]);
    p[i] = v;
    atomicAdd(&segsum[(long long)dst * H + h], v);
}

__global__ void edge_agg(const int* __restrict__ ei, int E_real, int E_tot,
                         const float* __restrict__ p, const float* __restrict__ segsum,
                         const float* __restrict__ xl, float* __restrict__ agg, int H, int D)
{
    long long w = ((long long)blockIdx.x * blockDim.x + threadIdx.x) >> 5;
    int lane = threadIdx.x & 31;
    if (w >= (long long)E_tot * H) return;
    int e = (int)(w / H), h = (int)(w % H);
    int src, dst;
    if (e < E_real) { src = ei[e]; dst = ei[E_real + e]; }
    else            { src = dst = e - E_real; }
    float alpha = p[(long long)e * H + h] / segsum[(long long)dst * H + h];
    const float* pl = xl + (long long)src * H * D + h * D;
    float* po = agg + (long long)dst * H * D + h * D;
    for (int d = lane; d < D; d += 32)
        atomicAdd(&po[d], alpha * pl[d]);
}

__global__ void bias_relu_k(const float* __restrict__ in, const float* __restrict__ bias,
                            float* __restrict__ out, long long total, int M)
{
    long long i = (long long)blockIdx.x * blockDim.x + threadIdx.x;
    if (i >= total) return;
    int c = (int)(i % M);
    out[i] = fmaxf(in[i] + bias[c], 0.0f);
}

// combined[n] = [building_features[n] (64), cx2[map[n]] (128)]
__global__ void build_combined(const float* __restrict__ bf, const float* __restrict__ cx,
                               const int* __restrict__ map, float* __restrict__ comb)
{
    long long i = (long long)blockIdx.x * blockDim.x + threadIdx.x;
    if (i >= (long long)NB * 192) return;
    int n = (int)(i / 192), c = (int)(i % 192);
    comb[i] = (c < 64) ? bf[(long long)n * 64 + c]
                       : cx[(long long)map[n] * 128 + (c - 64)];
}

// feature-attention output head: warp per node
__global__ void fa_out(const float* __restrict__ fah, const float* __restrict__ w2,
                       const float* __restrict__ b2, float* __restrict__ wmean)
{
    long long n = ((long long)blockIdx.x * blockDim.x + threadIdx.x) >> 5;
    int lane = threadIdx.x & 31;
    if (n >= NB) return;
    float m0 = 0.0f, m1 = 0.0f;
    for (int h = 0; h < 8; h++) {
        const float* ph = fah + n * 1024 + h * 128;
        const float* pw = w2 + h * 256;
        float s0 = 0.0f, s1 = 0.0f;
        for (int k = lane; k < 128; k += 32) {
            float v = ph[k];
            s0 += v * pw[k * 2 + 0];
            s1 += v * pw[k * 2 + 1];
        }
        #pragma unroll
        for (int o = 16; o; o >>= 1) {
            s0 += __shfl_down_sync(0xffffffffu, s0, o);
            s1 += __shfl_down_sync(0xffffffffu, s1, o);
        }
        if (lane == 0) {
            s0 += b2[h * 2]; s1 += b2[h * 2 + 1];
            float mx = fmaxf(s0, s1);
            float e0 = expf(s0 - mx), e1 = expf(s1 - mx);
            float inv = 1.0f / (e0 + e1);
            m0 += e0 * inv; m1 += e1 * inv;
        }
    }
    if (lane == 0) {
        wmean[n * 2 + 0] = m0 * 0.125f;
        wmean[n * 2 + 1] = m1 * 0.125f;
    }
}

__global__ void fuse_k(float* __restrict__ comb, const float* __restrict__ wmean)
{
    long long i = (long long)blockIdx.x * blockDim.x + threadIdx.x;
    if (i >= (long long)NB * 192) return;
    int n = (int)(i / 192), c = (int)(i % 192);
    comb[i] *= (c < 64) ? wmean[n * 2] : wmean[n * 2 + 1];
}

// layer-3 transforms: [N,128] @ [128,2] for wl and wr
__global__ void small_xform(const float* __restrict__ x, const float* __restrict__ wl,
                            const float* __restrict__ wr, float* __restrict__ xl,
                            float* __restrict__ xr, int N, int K)
{
    int n = blockIdx.x * blockDim.x + threadIdx.x;
    if (n >= N) return;
    float a0 = 0, a1 = 0, b0 = 0, b1 = 0;
    const float* px = x + (long long)n * K;
    for (int k = 0; k < K; k++) {
        float v = px[k];
        a0 += v * wl[k * 2]; a1 += v * wl[k * 2 + 1];
        b0 += v * wr[k * 2]; b1 += v * wr[k * 2 + 1];
    }
    xl[n * 2] = a0; xl[n * 2 + 1] = a1;
    xr[n * 2] = b0; xr[n * 2 + 1] = b1;
}

__global__ void final_lsm(const float* __restrict__ agg, const float* __restrict__ b,
                          float* __restrict__ out, int N)
{
    int n = blockIdx.x * blockDim.x + threadIdx.x;
    if (n >= N) return;
    float v0 = agg[n * 2] + b[0], v1 = agg[n * 2 + 1] + b[1];
    float mx = fmaxf(v0, v1);
    float lse = mx + logf(expf(v0 - mx) + expf(v1 - mx));
    out[n * 2] = v0 - lse;
    out[n * 2 + 1] = v1 - lse;
}

// ---------------------------------------------------------------------------
// Host orchestration
// ---------------------------------------------------------------------------
static inline int cdivll(long long a, long long b) { return (int)((a + b - 1) / b); }

static void fill(float* p, float v, long long n) {
    fillk<<<cdivll(n, 256), 256>>>(p, v, n);
}

static void gemm(const float* A, const float* B, float* C, const float* bias,
                 int N, int K, int M, int ldc, int relu)
{
    dim3 grid((M + BN - 1) / BN, (N + BM - 1) / BM);
    sgemm_bias_relu<<<grid, 256>>>(A, B, C, bias, N, K, M, ldc, relu);
}

static void run_gat_edges(const int* ei, int E_real, int Nnodes, int H, int D,
                          const float* xl, const float* xr, const float* att,
                          float* p, float* smax, float* ssum, float* agg)
{
    int E_tot = E_real + Nnodes;
    fill(smax, -INFINITY, (long long)Nnodes * H);
    fill(ssum, 0.0f, (long long)Nnodes * H);
    fill(agg, 0.0f, (long long)Nnodes * H * D);
    long long w = (long long)E_tot * H;
    edge_logits<<<cdivll(w * 32, 256), 256>>>(ei, E_real, E_tot, xl, xr, att, p, smax, H, D);
    edge_exp<<<cdivll(w, 256), 256>>>(ei, E_real, E_tot, p, smax, ssum, H);
    edge_agg<<<cdivll(w * 32, 256), 256>>>(ei, E_real, E_tot, p, ssum, xl, agg, H, D);
}

extern "C" void kernel_launch(void* const* d_in, const int* in_sizes, int n_in,
                              void* d_out, int out_size)
{
    // Resolve input ordering (setup_inputs dict order vs reference signature order)
    int idx_bf = 0, idx_cf = 1, idx_bei, idx_cei, idx_map, base_w;
    if (in_sizes[2] == 2 * EB) {        // edges right after features
        idx_bei = 2; idx_cei = 3; idx_map = 4; base_w = 5;
    } else {                            // weights after features, edges at the end
        base_w = 2; idx_bei = 26; idx_cei = 27; idx_map = 28;
    }
    const float* bf  = (const float*)d_in[idx_bf];
    const float* cf  = (const float*)d_in[idx_cf];
    const int*   bei = (const int*)d_in[idx_bei];
    const int*   cei = (const int*)d_in[idx_cei];
    const int*   b2c = (const int*)d_in[idx_map];

    enum { C1WL, C1WR, C1ATT, C1B, C2WL, C2WR, C2ATT, C2B,
           FAW1, FAB1, FAW2, FAB2,
           B1WL, B1WR, B1ATT, B1B, B2WL, B2WR, B2ATT, B2B,
           B3WL, B3WR, B3ATT, B3B };
    const float* W[24];
    for (int i = 0; i < 24; i++) W[i] = (const float*)d_in[base_w + i];

    float* S;
    cudaGetSymbolAddress((void**)&S, g_scratch);

    float* c_xl  = S + O_CXL;   float* c_xr  = S + O_CXR;
    float* c_h1  = S + O_CH1;   float* c_agg = S + O_CAGG;
    float* c_xl2 = S + O_CXL2;  float* c_xr2 = S + O_CXR2;
    float* c_h2  = S + O_CH2;   float* ce_p  = S + O_CEP;
    float* c_max = S + O_CMAX;  float* c_sum = S + O_CSUM;
    float* comb  = S + O_COMB;  float* fah   = S + O_FAH;
    float* wmean = S + O_WM;
    float* b_xl  = S + O_BXL;   float* b_xr  = S + O_BXR;
    float* b_agg = S + O_BAGG;  float* b_h1  = S + O_BH1;
    float* b_h2  = S + O_BH2;   float* be_p  = S + O_BEP;
    float* b_max = S + O_BMAX;  float* b_sum = S + O_BSUM;
    float* xl3   = S + O_XL3;   float* xr3   = S + O_XR3;
    float* agg3  = S + O_AGG3;

    // ---- Community GNN ----
    // Layer 1: 32 -> 8 x 64
    gemm(cf, W[C1WL], c_xl, nullptr, NC, 32, 512, 512, 0);
    gemm(cf, W[C1WR], c_xr, nullptr, NC, 32, 512, 512, 0);
    run_gat_edges(cei, EC, NC, 8, 64, c_xl, c_xr, W[C1ATT], ce_p, c_max, c_sum, c_agg);
    bias_relu_k<<<cdivll((long long)NC * 512, 256), 256>>>(c_agg, W[C1B], c_h1, (long long)NC * 512, 512);
    // Layer 2: 512 -> 4 x 32
    gemm(c_h1, W[C2WL], c_xl2, nullptr, NC, 512, 128, 128, 0);
    gemm(c_h1, W[C2WR], c_xr2, nullptr, NC, 512, 128, 128, 0);
    run_gat_edges(cei, EC, NC, 4, 32, c_xl2, c_xr2, W[C2ATT], ce_p, c_max, c_sum, c_agg);
    bias_relu_k<<<cdivll((long long)NC * 128, 256), 256>>>(c_agg, W[C2B], c_h2, (long long)NC * 128, 128);

    // ---- Feature-attention fusion ----
    build_combined<<<cdivll((long long)NB * 192, 256), 256>>>(bf, c_h2, b2c, comb);
    for (int h = 0; h < 8; h++)
        gemm(comb, W[FAW1] + (long long)h * 192 * 128, fah + h * 128, W[FAB1] + h * 128,
             NB, 192, 128, 1024, 1);
    fa_out<<<cdivll((long long)NB * 32, 256), 256>>>(fah, W[FAW2], W[FAB2], wmean);
    fuse_k<<<cdivll((long long)NB * 192, 256), 256>>>(comb, wmean);

    // ---- Building GNN ----
    // Layer 1: 192 -> 8 x 64
    gemm(comb, W[B1WL], b_xl, nullptr, NB, 192, 512, 512, 0);
    gemm(comb, W[B1WR], b_xr, nullptr, NB, 192, 512, 512, 0);
    run_gat_edges(bei, EB, NB, 8, 64, b_xl, b_xr, W[B1ATT], be_p, b_max, b_sum, b_agg);
    bias_relu_k<<<cdivll((long long)NB * 512, 256), 256>>>(b_agg, W[B1B], b_h1, (long long)NB * 512, 512);
    // Layer 2: 512 -> 4 x 32 (reuse b_xl/b_xr/b_agg as [NB,128])
    gemm(b_h1, W[B2WL], b_xl, nullptr, NB, 512, 128, 128, 0);
    gemm(b_h1, W[B2WR], b_xr, nullptr, NB, 512, 128, 128, 0);
    run_gat_edges(bei, EB, NB, 4, 32, b_xl, b_xr, W[B2ATT], be_p, b_max, b_sum, b_agg);
    bias_relu_k<<<cdivll((long long)NB * 128, 256), 256>>>(b_agg, W[B2B], b_h2, (long long)NB * 128, 128);
    // Layer 3: 128 -> 1 x 2
    small_xform<<<cdivll(NB, 256), 256>>>(b_h2, W[B3WL], W[B3WR], xl3, xr3, NB, 128);
    run_gat_edges(bei, EB, NB, 1, 2, xl3, xr3, W[B3ATT], be_p, b_max, b_sum, agg3);
    final_lsm<<<cdivll(NB, 256), 256>>>(agg3, W[B3B], (float*)d_out, NB);
}

// round 4
// speedup vs baseline: 1.5713x; 1.5713x over previous
#include <cuda_runtime.h>
#include <math.h>

// Problem constants
#define NB 100000
#define NC 10000
#define EB 400000
#define EC 80000
#define ECT (EC + NC)
#define EBT (EB + NB)

// ---------------------------------------------------------------------------
// Scratch
// ---------------------------------------------------------------------------
constexpr long long O_CXL  = 0;
constexpr long long O_CXR  = O_CXL  + (long long)NC * 512;
constexpr long long O_CH1  = O_CXR  + (long long)NC * 512;
constexpr long long O_CAGG = O_CH1  + (long long)NC * 512;
constexpr long long O_CXL2 = O_CAGG + (long long)NC * 512;
constexpr long long O_CXR2 = O_CXL2 + (long long)NC * 128;
constexpr long long O_CH2  = O_CXR2 + (long long)NC * 128;
constexpr long long O_CEP  = O_CH2  + (long long)NC * 128;
constexpr long long O_CMAX = O_CEP  + (long long)ECT * 8;
constexpr long long O_CSUM = O_CMAX + (long long)NC * 8;
constexpr long long O_COMB = O_CSUM + (long long)NC * 8;
constexpr long long O_FAH  = O_COMB + (long long)NB * 192;
constexpr long long O_WM   = O_FAH  + (long long)NB * 1024;
constexpr long long O_FAW  = O_WM   + (long long)NB * 2;
constexpr long long O_BXL  = O_FAW  + (long long)192 * 1024;
constexpr long long O_BXR  = O_BXL  + (long long)NB * 512;
constexpr long long O_BAGG = O_BXR  + (long long)NB * 512;
constexpr long long O_BH1  = O_BAGG + (long long)NB * 512;
constexpr long long O_BH2  = O_BH1  + (long long)NB * 512;
constexpr long long O_BEP  = O_BH2  + (long long)NB * 128;
constexpr long long O_BMAX = O_BEP  + (long long)EBT * 8;
constexpr long long O_BSUM = O_BMAX + (long long)NB * 8;
constexpr long long O_XL3  = O_BSUM + (long long)NB * 8;
constexpr long long O_XR3  = O_XL3  + (long long)NB * 2;
constexpr long long O_AGG3 = O_XR3  + (long long)NB * 2;
constexpr long long SCRATCH_TOTAL = O_AGG3 + (long long)NB * 2;

__device__ float g_scratch[SCRATCH_TOTAL];

// ---------------------------------------------------------------------------
__device__ __forceinline__ void atomicMaxF(float* addr, float v) {
    if (v >= 0.0f) atomicMax((int*)addr, __float_as_int(v));
    else           atomicMin((unsigned int*)addr, __float_as_uint(v));
}

__global__ void fillk(float* __restrict__ x, float v, long long n) {
    long long i = (long long)blockIdx.x * blockDim.x + threadIdx.x;
    if (i < n) x[i] = v;
}

// ---------------------------------------------------------------------------
// SGEMM: C[N,M] = A[N,K] @ B[K,M] (+bias, optional relu)
// 128x128 block, 8x8 per thread, 256 threads, float4 loads, reg prefetch.
// Requires: K % 16 == 0, M % 128 == 0.
// ---------------------------------------------------------------------------
#define TBM 128
#define TBN 128
#define TBK 16

__global__ void __launch_bounds__(256) sgemm128(
    const float* __restrict__ A, const float* __restrict__ B,
    float* __restrict__ C, const float* __restrict__ bias,
    int N, int K, int M, int relu)
{
    __shared__ float As[TBK][TBM + 4];
    __shared__ float Bs[TBK][TBN + 4];
    int tid = threadIdx.x;
    int rowBase = blockIdx.y * TBM;
    int colBase = blockIdx.x * TBN;
    int tx = tid & 15, ty = tid >> 4;

    int aRow = tid >> 2;            // 0..63
    int aK   = (tid & 3) << 2;      // 0,4,8,12
    int bK   = tid >> 5;            // 0..7
    int bCol = (tid & 31) << 2;     // 0..124

    float4 ra[2], rb[2];
    #pragma unroll
    for (int l = 0; l < 2; l++) {
        int gr = rowBase + aRow + l * 64;
        ra[l] = make_float4(0.f, 0.f, 0.f, 0.f);
        if (gr < N) ra[l] = *(const float4*)(A + (long long)gr * K + aK);
        rb[l] = *(const float4*)(B + (long long)(bK + l * 8) * M + colBase + bCol);
    }

    float acc[8][8] = {};
    for (int k0 = 0; k0 < K; k0 += TBK) {
        #pragma unroll
        for (int l = 0; l < 2; l++) {
            int r = aRow + l * 64;
            As[aK + 0][r] = ra[l].x; As[aK + 1][r] = ra[l].y;
            As[aK + 2][r] = ra[l].z; As[aK + 3][r] = ra[l].w;
            *(float4*)&Bs[bK + l * 8][bCol] = rb[l];
        }
        __syncthreads();

        int k1 = k0 + TBK;
        if (k1 < K) {
            #pragma unroll
            for (int l = 0; l < 2; l++) {
                int gr = rowBase + aRow + l * 64;
                ra[l] = make_float4(0.f, 0.f, 0.f, 0.f);
                if (gr < N) ra[l] = *(const float4*)(A + (long long)gr * K + k1 + aK);
                rb[l] = *(const float4*)(B + (long long)(k1 + bK + l * 8) * M + colBase + bCol);
            }
        }

        #pragma unroll
        for (int kk = 0; kk < TBK; kk++) {
            float a[8], b[8];
            #pragma unroll
            for (int i = 0; i < 8; i++) a[i] = As[kk][ty * 8 + i];
            #pragma unroll
            for (int j = 0; j < 8; j++) b[j] = Bs[kk][tx * 8 + j];
            #pragma unroll
            for (int i = 0; i < 8; i++)
                #pragma unroll
                for (int j = 0; j < 8; j++)
                    acc[i][j] = fmaf(a[i], b[j], acc[i][j]);
        }
        __syncthreads();
    }

    #pragma unroll
    for (int i = 0; i < 8; i++) {
        int r = rowBase + ty * 8 + i;
        if (r >= N) continue;
        #pragma unroll
        for (int j = 0; j < 8; j += 4) {
            int c = colBase + tx * 8 + j;
            float4 v = make_float4(acc[i][j], acc[i][j+1], acc[i][j+2], acc[i][j+3]);
            if (bias) { v.x += bias[c]; v.y += bias[c+1]; v.z += bias[c+2]; v.w += bias[c+3]; }
            if (relu) { v.x = fmaxf(v.x, 0.f); v.y = fmaxf(v.y, 0.f);
                        v.z = fmaxf(v.z, 0.f); v.w = fmaxf(v.w, 0.f); }
            *(float4*)(C + (long long)r * M + c) = v;
        }
    }
}

// ---------------------------------------------------------------------------
// GATv2 edge kernels, LPG lanes per (edge, head) group.
// ---------------------------------------------------------------------------
template<int LPG, int D>
__global__ void edge_logits_t(const int* __restrict__ ei, int E_real, long long ngroups,
                              const float* __restrict__ xl, const float* __restrict__ xr,
                              const float* __restrict__ att, float* __restrict__ p,
                              float* __restrict__ segmax, int H)
{
    long long t = (long long)blockIdx.x * blockDim.x + threadIdx.x;
    long long g = t / LPG;
    int lane = (int)(t % LPG);
    bool valid = g < ngroups;
    int h = 0, dst = 0;
    float s = 0.0f;
    if (valid) {
        int e = (int)(g / H); h = (int)(g % H);
        int src;
        if (e < E_real) { src = ei[e]; dst = ei[E_real + e]; }
        else            { src = dst = e - E_real; }
        const float* pl = xl + ((long long)src * H + h) * D;
        const float* pr = xr + ((long long)dst * H + h) * D;
        const float* pa = att + h * D;
        #pragma unroll
        for (int d = lane; d < D; d += LPG) {
            float v = pl[d] + pr[d];
            v = v > 0.0f ? v : 0.2f * v;
            s += v * pa[d];
        }
    }
    #pragma unroll
    for (int o = LPG / 2; o; o >>= 1) s += __shfl_down_sync(0xffffffffu, s, o, LPG);
    if (valid && lane == 0) {
        p[g] = s;
        atomicMaxF(&segmax[(long long)dst * H + h], s);
    }
}

__global__ void edge_exp(const int* __restrict__ ei, int E_real, long long total,
                         float* __restrict__ p, const float* __restrict__ segmax,
                         float* __restrict__ segsum, int H)
{
    long long i = (long long)blockIdx.x * blockDim.x + threadIdx.x;
    if (i >= total) return;
    int e = (int)(i / H), h = (int)(i % H);
    int dst = (e < E_real) ? ei[E_real + e] : e - E_real;
    float v = expf(p[i] - segmax[(long long)dst * H + h]);
    p[i] = v;
    atomicAdd(&segsum[(long long)dst * H + h], v);
}

template<int LPG, int D>
__global__ void edge_agg_t(const int* __restrict__ ei, int E_real, long long ngroups,
                           const float* __restrict__ p, const float* __restrict__ segsum,
                           const float* __restrict__ xl, float* __restrict__ agg, int H)
{
    long long t = (long long)blockIdx.x * blockDim.x + threadIdx.x;
    long long g = t / LPG;
    int lane = (int)(t % LPG);
    if (g >= ngroups) return;
    int e = (int)(g / H), h = (int)(g % H);
    int src, dst;
    if (e < E_real) { src = ei[e]; dst = ei[E_real + e]; }
    else            { src = dst = e - E_real; }
    float alpha = p[g] / segsum[(long long)dst * H + h];
    const float* pl = xl + ((long long)src * H + h) * D;
    float* po = agg + ((long long)dst * H + h) * D;
    #pragma unroll
    for (int d = lane; d < D; d += LPG)
        atomicAdd(&po[d], alpha * pl[d]);
}

__global__ void bias_relu_k(const float* __restrict__ in, const float* __restrict__ bias,
                            float* __restrict__ out, long long total, int M)
{
    long long i = (long long)blockIdx.x * blockDim.x + threadIdx.x;
    if (i >= total) return;
    int c = (int)(i % M);
    out[i] = fmaxf(in[i] + bias[c], 0.0f);
}

__global__ void build_combined(const float* __restrict__ bf, const float* __restrict__ cx,
                               const int* __restrict__ map, float* __restrict__ comb)
{
    long long i = (long long)blockIdx.x * blockDim.x + threadIdx.x;
    if (i >= (long long)NB * 192) return;
    int n = (int)(i / 192), c = (int)(i % 192);
    comb[i] = (c < 64) ? bf[(long long)n * 64 + c]
                       : cx[(long long)map[n] * 128 + (c - 64)];
}

// fa_w1 (8,192,128) -> [192, 1024] with col = h*128 + j
__global__ void transpose_faw1(const float* __restrict__ w, float* __restrict__ out)
{
    int i = blockIdx.x * blockDim.x + threadIdx.x;
    if (i >= 8 * 192 * 128) return;
    int h = i / (192 * 128), r = (i / 128) % 192, j = i % 128;
    out[r * 1024 + h * 128 + j] = w[i];
}

__global__ void fa_out(const float* __restrict__ fah, const float* __restrict__ w2,
                       const float* __restrict__ b2, float* __restrict__ wmean)
{
    long long n = ((long long)blockIdx.x * blockDim.x + threadIdx.x) >> 5;
    int lane = threadIdx.x & 31;
    if (n >= NB) return;
    float m0 = 0.0f, m1 = 0.0f;
    for (int h = 0; h < 8; h++) {
        const float* ph = fah + n * 1024 + h * 128;
        const float* pw = w2 + h * 256;
        float s0 = 0.0f, s1 = 0.0f;
        for (int k = lane; k < 128; k += 32) {
            float v = ph[k];
            s0 += v * pw[k * 2 + 0];
            s1 += v * pw[k * 2 + 1];
        }
        #pragma unroll
        for (int o = 16; o; o >>= 1) {
            s0 += __shfl_down_sync(0xffffffffu, s0, o);
            s1 += __shfl_down_sync(0xffffffffu, s1, o);
        }
        if (lane == 0) {
            s0 += b2[h * 2]; s1 += b2[h * 2 + 1];
            float mx = fmaxf(s0, s1);
            float e0 = expf(s0 - mx), e1 = expf(s1 - mx);
            float inv = 1.0f / (e0 + e1);
            m0 += e0 * inv; m1 += e1 * inv;
        }
    }
    if (lane == 0) {
        wmean[n * 2 + 0] = m0 * 0.125f;
        wmean[n * 2 + 1] = m1 * 0.125f;
    }
}

__global__ void fuse_k(float* __restrict__ comb, const float* __restrict__ wmean)
{
    long long i = (long long)blockIdx.x * blockDim.x + threadIdx.x;
    if (i >= (long long)NB * 192) return;
    int n = (int)(i / 192), c = (int)(i % 192);
    comb[i] *= (c < 64) ? wmean[n * 2] : wmean[n * 2 + 1];
}

__global__ void small_xform(const float* __restrict__ x, const float* __restrict__ wl,
                            const float* __restrict__ wr, float* __restrict__ xl,
                            float* __restrict__ xr, int N, int K)
{
    int n = blockIdx.x * blockDim.x + threadIdx.x;
    if (n >= N) return;
    float a0 = 0, a1 = 0, b0 = 0, b1 = 0;
    const float* px = x + (long long)n * K;
    for (int k = 0; k < K; k++) {
        float v = px[k];
        a0 += v * wl[k * 2]; a1 += v * wl[k * 2 + 1];
        b0 += v * wr[k * 2]; b1 += v * wr[k * 2 + 1];
    }
    xl[n * 2] = a0; xl[n * 2 + 1] = a1;
    xr[n * 2] = b0; xr[n * 2 + 1] = b1;
}

__global__ void final_lsm(const float* __restrict__ agg, const float* __restrict__ b,
                          float* __restrict__ out, int N)
{
    int n = blockIdx.x * blockDim.x + threadIdx.x;
    if (n >= N) return;
    float v0 = agg[n * 2] + b[0], v1 = agg[n * 2 + 1] + b[1];
    float mx = fmaxf(v0, v1);
    float lse = mx + logf(expf(v0 - mx) + expf(v1 - mx));
    out[n * 2] = v0 - lse;
    out[n * 2 + 1] = v1 - lse;
}

// ---------------------------------------------------------------------------
static inline int cdivll(long long a, long long b) { return (int)((a + b - 1) / b); }

static void fill(float* p, float v, long long n) {
    fillk<<<cdivll(n, 256), 256>>>(p, v, n);
}

static void gemm(const float* A, const float* B, float* C, const float* bias,
                 int N, int K, int M, int relu)
{
    dim3 grid((M + TBN - 1) / TBN, (N + TBM - 1) / TBM);
    sgemm128<<<grid, 256>>>(A, B, C, bias, N, K, M, relu);
}

template<int LPG, int D>
static void run_gat_edges(const int* ei, int E_real, int Nnodes, int H,
                          const float* xl, const float* xr, const float* att,
                          float* p, float* smax, float* ssum, float* agg)
{
    int E_tot = E_real + Nnodes;
    fill(smax, -INFINITY, (long long)Nnodes * H);
    fill(ssum, 0.0f, (long long)Nnodes * H);
    fill(agg, 0.0f, (long long)Nnodes * H * D);
    long long ngroups = (long long)E_tot * H;
    edge_logits_t<LPG, D><<<cdivll(ngroups * LPG, 256), 256>>>(ei, E_real, ngroups, xl, xr, att, p, smax, H);
    edge_exp<<<cdivll(ngroups, 256), 256>>>(ei, E_real, ngroups, p, smax, ssum, H);
    edge_agg_t<LPG, D><<<cdivll(ngroups * LPG, 256), 256>>>(ei, E_real, ngroups, p, ssum, xl, agg, H);
}

extern "C" void kernel_launch(void* const* d_in, const int* in_sizes, int n_in,
                              void* d_out, int out_size)
{
    int idx_bf = 0, idx_cf = 1, idx_bei, idx_cei, idx_map, base_w;
    if (in_sizes[2] == 2 * EB) { idx_bei = 2; idx_cei = 3; idx_map = 4; base_w = 5; }
    else                       { base_w = 2; idx_bei = 26; idx_cei = 27; idx_map = 28; }
    const float* bf  = (const float*)d_in[idx_bf];
    const float* cf  = (const float*)d_in[idx_cf];
    const int*   bei = (const int*)d_in[idx_bei];
    const int*   cei = (const int*)d_in[idx_cei];
    const int*   b2c = (const int*)d_in[idx_map];

    enum { C1WL, C1WR, C1ATT, C1B, C2WL, C2WR, C2ATT, C2B,
           FAW1, FAB1, FAW2, FAB2,
           B1WL, B1WR, B1ATT, B1B, B2WL, B2WR, B2ATT, B2B,
           B3WL, B3WR, B3ATT, B3B };
    const float* W[24];
    for (int i = 0; i < 24; i++) W[i] = (const float*)d_in[base_w + i];

    float* S;
    cudaGetSymbolAddress((void**)&S, g_scratch);

    float* c_xl  = S + O_CXL;   float* c_xr  = S + O_CXR;
    float* c_h1  = S + O_CH1;   float* c_agg = S + O_CAGG;
    float* c_xl2 = S + O_CXL2;  float* c_xr2 = S + O_CXR2;
    float* c_h2  = S + O_CH2;   float* ce_p  = S + O_CEP;
    float* c_max = S + O_CMAX;  float* c_sum = S + O_CSUM;
    float* comb  = S + O_COMB;  float* fah   = S + O_FAH;
    float* wmean = S + O_WM;    float* faW   = S + O_FAW;
    float* b_xl  = S + O_BXL;   float* b_xr  = S + O_BXR;
    float* b_agg = S + O_BAGG;  float* b_h1  = S + O_BH1;
    float* b_h2  = S + O_BH2;   float* be_p  = S + O_BEP;
    float* b_max = S + O_BMAX;  float* b_sum = S + O_BSUM;
    float* xl3   = S + O_XL3;   float* xr3   = S + O_XR3;
    float* agg3  = S + O_AGG3;

    // ---- Community GNN ----
    gemm(cf, W[C1WL], c_xl, nullptr, NC, 32, 512, 0);
    gemm(cf, W[C1WR], c_xr, nullptr, NC, 32, 512, 0);
    run_gat_edges<32, 64>(cei, EC, NC, 8, c_xl, c_xr, W[C1ATT], ce_p, c_max, c_sum, c_agg);
    bias_relu_k<<<cdivll((long long)NC * 512, 256), 256>>>(c_agg, W[C1B], c_h1, (long long)NC * 512, 512);

    gemm(c_h1, W[C2WL], c_xl2, nullptr, NC, 512, 128, 0);
    gemm(c_h1, W[C2WR], c_xr2, nullptr, NC, 512, 128, 0);
    run_gat_edges<16, 32>(cei, EC, NC, 4, c_xl2, c_xr2, W[C2ATT], ce_p, c_max, c_sum, c_agg);
    bias_relu_k<<<cdivll((long long)NC * 128, 256), 256>>>(c_agg, W[C2B], c_h2, (long long)NC * 128, 128);

    // ---- Feature-attention fusion ----
    build_combined<<<cdivll((long long)NB * 192, 256), 256>>>(bf, c_h2, b2c, comb);
    transpose_faw1<<<cdivll(8 * 192 * 128, 256), 256>>>(W[FAW1], faW);
    gemm(comb, faW, fah, W[FAB1], NB, 192, 1024, 1);
    fa_out<<<cdivll((long long)NB * 32, 256), 256>>>(fah, W[FAW2], W[FAB2], wmean);
    fuse_k<<<cdivll((long long)NB * 192, 256), 256>>>(comb, wmean);

    // ---- Building GNN ----
    gemm(comb, W[B1WL], b_xl, nullptr, NB, 192, 512, 0);
    gemm(comb, W[B1WR], b_xr, nullptr, NB, 192, 512, 0);
    run_gat_edges<32, 64>(bei, EB, NB, 8, b_xl, b_xr, W[B1ATT], be_p, b_max, b_sum, b_agg);
    bias_relu_k<<<cdivll((long long)NB * 512, 256), 256>>>(b_agg, W[B1B], b_h1, (long long)NB * 512, 512);

    gemm(b_h1, W[B2WL], b_xl, nullptr, NB, 512, 128, 0);
    gemm(b_h1, W[B2WR], b_xr, nullptr, NB, 512, 128, 0);
    run_gat_edges<16, 32>(bei, EB, NB, 4, b_xl, b_xr, W[B2ATT], be_p, b_max, b_sum, b_agg);
    bias_relu_k<<<cdivll((long long)NB * 128, 256), 256>>>(b_agg, W[B2B], b_h2, (long long)NB * 128, 128);

    small_xform<<<cdivll(NB, 256), 256>>>(b_h2, W[B3WL], W[B3WR], xl3, xr3, NB, 128);
    run_gat_edges<2, 2>(bei, EB, NB, 1, xl3, xr3, W[B3ATT], be_p, b_max, b_sum, agg3);
    final_lsm<<<cdivll(NB, 256), 256>>>(agg3, W[B3B], (float*)d_out, NB);
}

// round 5
// speedup vs baseline: 2.1539x; 1.3708x over previous
#include <cuda_runtime.h>
#include <math.h>

// Problem constants
#define NB 100000
#define NC 10000
#define EB 400000
#define EC 80000
#define ECT (EC + NC)
#define EBT (EB + NB)

// ---------------------------------------------------------------------------
// Scratch
// ---------------------------------------------------------------------------
constexpr long long O_CXL  = 0;
constexpr long long O_CXR  = O_CXL  + (long long)NC * 512;
constexpr long long O_CH1  = O_CXR  + (long long)NC * 512;
constexpr long long O_CAGG = O_CH1  + (long long)NC * 512;
constexpr long long O_CXL2 = O_CAGG + (long long)NC * 512;
constexpr long long O_CXR2 = O_CXL2 + (long long)NC * 128;
constexpr long long O_CH2  = O_CXR2 + (long long)NC * 128;
constexpr long long O_CEP  = O_CH2  + (long long)NC * 128;
constexpr long long O_CMAX = O_CEP  + (long long)ECT * 8;
constexpr long long O_CSUM = O_CMAX + (long long)NC * 8;
constexpr long long O_COMB = O_CSUM + (long long)NC * 8;
constexpr long long O_FAH  = O_COMB + (long long)NB * 192;
constexpr long long O_WM   = O_FAH  + (long long)NB * 1024;
constexpr long long O_FAW  = O_WM   + (long long)NB * 2;
constexpr long long O_BXL  = O_FAW  + (long long)192 * 1024;
constexpr long long O_BXR  = O_BXL  + (long long)NB * 512;
constexpr long long O_BAGG = O_BXR  + (long long)NB * 512;
constexpr long long O_BH1  = O_BAGG + (long long)NB * 512;
constexpr long long O_BH2  = O_BH1  + (long long)NB * 512;
constexpr long long O_BEP  = O_BH2  + (long long)NB * 128;
constexpr long long O_BMAX = O_BEP  + (long long)EBT * 8;
constexpr long long O_BSUM = O_BMAX + (long long)NB * 8;
constexpr long long O_XL3  = O_BSUM + (long long)NB * 8;
constexpr long long O_XR3  = O_XL3  + (long long)NB * 2;
constexpr long long O_AGG3 = O_XR3  + (long long)NB * 2;
constexpr long long SCRATCH_TOTAL = O_AGG3 + (long long)NB * 2;

__device__ float g_scratch[SCRATCH_TOTAL];

// ---------------------------------------------------------------------------
__device__ __forceinline__ void atomicMaxF(float* addr, float v) {
    if (v >= 0.0f) atomicMax((int*)addr, __float_as_int(v));
    else           atomicMin((unsigned int*)addr, __float_as_uint(v));
}

__global__ void fillk(float* __restrict__ x, float v, long long n) {
    long long i = (long long)blockIdx.x * blockDim.x + threadIdx.x;
    if (i < n) x[i] = v;
}

// ---------------------------------------------------------------------------
// TF32 tensor-core GEMM: C[N,M] = A[N,K] @ B[K,M] (+bias, optional relu)
// 128x128x32 CTA tile, 8 warps (2x4), warp tile 64x32, mma.m16n8k8.tf32.
// Requires: K % 32 == 0, M % 128 == 0.
// ---------------------------------------------------------------------------
#define MM_BM 128
#define MM_BN 128
#define MM_BK 32

__device__ __forceinline__ unsigned f2tf32(float x) {
    unsigned r;
    asm("cvt.rna.tf32.f32 %0, %1;" : "=r"(r) : "f"(x));
    return r;
}

__device__ __forceinline__ void mma_tf32(float* c, unsigned a0, unsigned a1,
                                         unsigned a2, unsigned a3,
                                         unsigned b0, unsigned b1) {
    asm volatile(
        "mma.sync.aligned.m16n8k8.row.col.f32.tf32.tf32.f32 "
        "{%0,%1,%2,%3},{%4,%5,%6,%7},{%8,%9},{%0,%1,%2,%3};"
        : "+f"(c[0]), "+f"(c[1]), "+f"(c[2]), "+f"(c[3])
        : "r"(a0), "r"(a1), "r"(a2), "r"(a3), "r"(b0), "r"(b1));
}

__global__ void __launch_bounds__(256, 2) tf32gemm(
    const float* __restrict__ A, const float* __restrict__ B,
    float* __restrict__ C, const float* __restrict__ bias,
    int N, int K, int M, int relu)
{
    __shared__ unsigned As[MM_BK][MM_BM + 4];   // [k][m], tf32 bits
    __shared__ unsigned Bs[MM_BK][MM_BN + 4];   // [k][n], tf32 bits

    int tid = threadIdx.x;
    int warp = tid >> 5, lane = tid & 31;
    int wm = (warp >> 2) * 64;       // 0 / 64
    int wn = (warp & 3) * 32;        // 0,32,64,96
    int g  = lane >> 2;              // 0..7
    int tg = lane & 3;               // 0..3
    int rowBase = blockIdx.y * MM_BM;
    int colBase = blockIdx.x * MM_BN;

    // Loader mapping
    int aRow0 = tid >> 3;            // 0..31 (+32 per iter, 4 iters = 128 rows)
    int aK    = (tid & 7) << 2;      // 0..28
    int bK0   = tid >> 5;            // 0..7 (+8 per iter)
    int bN    = (lane) << 2;         // 0..124

    float acc[4][4][4] = {};         // [mi][nj][reg]

    for (int k0 = 0; k0 < K; k0 += MM_BK) {
        // Load A tile (128 x 32) -> As[k][m]
        #pragma unroll
        for (int it = 0; it < 4; it++) {
            int r = aRow0 + it * 32;
            int gr = rowBase + r;
            float4 v = make_float4(0.f, 0.f, 0.f, 0.f);
            if (gr < N) v = *(const float4*)(A + (long long)gr * K + k0 + aK);
            As[aK + 0][r] = f2tf32(v.x);
            As[aK + 1][r] = f2tf32(v.y);
            As[aK + 2][r] = f2tf32(v.z);
            As[aK + 3][r] = f2tf32(v.w);
        }
        // Load B tile (32 x 128) -> Bs[k][n]
        #pragma unroll
        for (int it = 0; it < 4; it++) {
            int kk = bK0 + it * 8;
            float4 v = *(const float4*)(B + (long long)(k0 + kk) * M + colBase + bN);
            Bs[kk][bN + 0] = f2tf32(v.x);
            Bs[kk][bN + 1] = f2tf32(v.y);
            Bs[kk][bN + 2] = f2tf32(v.z);
            Bs[kk][bN + 3] = f2tf32(v.w);
        }
        __syncthreads();

        #pragma unroll
        for (int ks = 0; ks < MM_BK; ks += 8) {
            unsigned af[4][4], bf[4][2];
            #pragma unroll
            for (int mi = 0; mi < 4; mi++) {
                int m = wm + mi * 16 + g;
                af[mi][0] = As[ks + tg][m];
                af[mi][1] = As[ks + tg][m + 8];
                af[mi][2] = As[ks + tg + 4][m];
                af[mi][3] = As[ks + tg + 4][m + 8];
            }
            #pragma unroll
            for (int nj = 0; nj < 4; nj++) {
                int n = wn + nj * 8 + g;
                bf[nj][0] = Bs[ks + tg][n];
                bf[nj][1] = Bs[ks + tg + 4][n];
            }
            #pragma unroll
            for (int mi = 0; mi < 4; mi++)
                #pragma unroll
                for (int nj = 0; nj < 4; nj++)
                    mma_tf32(acc[mi][nj], af[mi][0], af[mi][1], af[mi][2], af[mi][3],
                             bf[nj][0], bf[nj][1]);
        }
        __syncthreads();
    }

    // Epilogue: c0,c1 at (row, col..col+1); c2,c3 at (row+8, ...)
    #pragma unroll
    for (int mi = 0; mi < 4; mi++) {
        #pragma unroll
        for (int nj = 0; nj < 4; nj++) {
            int row = rowBase + wm + mi * 16 + g;
            int col = colBase + wn + nj * 8 + tg * 2;
            float b0 = 0.f, b1 = 0.f;
            if (bias) { b0 = bias[col]; b1 = bias[col + 1]; }
            if (row < N) {
                float2 v = make_float2(acc[mi][nj][0] + b0, acc[mi][nj][1] + b1);
                if (relu) { v.x = fmaxf(v.x, 0.f); v.y = fmaxf(v.y, 0.f); }
                *(float2*)(C + (long long)row * M + col) = v;
            }
            if (row + 8 < N) {
                float2 v = make_float2(acc[mi][nj][2] + b0, acc[mi][nj][3] + b1);
                if (relu) { v.x = fmaxf(v.x, 0.f); v.y = fmaxf(v.y, 0.f); }
                *(float2*)(C + (long long)(row + 8) * M + col) = v;
            }
        }
    }
}

// ---------------------------------------------------------------------------
// GATv2 edge kernels, LPG lanes per (edge, head) group.
// ---------------------------------------------------------------------------
template<int LPG, int D>
__global__ void edge_logits_t(const int* __restrict__ ei, int E_real, long long ngroups,
                              const float* __restrict__ xl, const float* __restrict__ xr,
                              const float* __restrict__ att, float* __restrict__ p,
                              float* __restrict__ segmax, int H)
{
    long long t = (long long)blockIdx.x * blockDim.x + threadIdx.x;
    long long g = t / LPG;
    int lane = (int)(t % LPG);
    bool valid = g < ngroups;
    int h = 0, dst = 0;
    float s = 0.0f;
    if (valid) {
        int e = (int)(g / H); h = (int)(g % H);
        int src;
        if (e < E_real) { src = ei[e]; dst = ei[E_real + e]; }
        else            { src = dst = e - E_real; }
        const float* pl = xl + ((long long)src * H + h) * D;
        const float* pr = xr + ((long long)dst * H + h) * D;
        const float* pa = att + h * D;
        #pragma unroll
        for (int d = lane; d < D; d += LPG) {
            float v = pl[d] + pr[d];
            v = v > 0.0f ? v : 0.2f * v;
            s += v * pa[d];
        }
    }
    #pragma unroll
    for (int o = LPG / 2; o; o >>= 1) s += __shfl_down_sync(0xffffffffu, s, o, LPG);
    if (valid && lane == 0) {
        p[g] = s;
        atomicMaxF(&segmax[(long long)dst * H + h], s);
    }
}

__global__ void edge_exp(const int* __restrict__ ei, int E_real, long long total,
                         float* __restrict__ p, const float* __restrict__ segmax,
                         float* __restrict__ segsum, int H)
{
    long long i = (long long)blockIdx.x * blockDim.x + threadIdx.x;
    if (i >= total) return;
    int e = (int)(i / H), h = (int)(i % H);
    int dst = (e < E_real) ? ei[E_real + e] : e - E_real;
    float v = expf(p[i] - segmax[(long long)dst * H + h]);
    p[i] = v;
    atomicAdd(&segsum[(long long)dst * H + h], v);
}

template<int LPG, int D>
__global__ void edge_agg_t(const int* __restrict__ ei, int E_real, long long ngroups,
                           const float* __restrict__ p, const float* __restrict__ segsum,
                           const float* __restrict__ xl, float* __restrict__ agg, int H)
{
    long long t = (long long)blockIdx.x * blockDim.x + threadIdx.x;
    long long g = t / LPG;
    int lane = (int)(t % LPG);
    if (g >= ngroups) return;
    int e = (int)(g / H), h = (int)(g % H);
    int src, dst;
    if (e < E_real) { src = ei[e]; dst = ei[E_real + e]; }
    else            { src = dst = e - E_real; }
    float alpha = p[g] / segsum[(long long)dst * H + h];
    const float* pl = xl + ((long long)src * H + h) * D;
    float* po = agg + ((long long)dst * H + h) * D;
    #pragma unroll
    for (int d = lane; d < D; d += LPG)
        atomicAdd(&po[d], alpha * pl[d]);
}

__global__ void bias_relu_k(const float* __restrict__ in, const float* __restrict__ bias,
                            float* __restrict__ out, long long total, int M)
{
    long long i = (long long)blockIdx.x * blockDim.x + threadIdx.x;
    if (i >= total) return;
    int c = (int)(i % M);
    out[i] = fmaxf(in[i] + bias[c], 0.0f);
}

__global__ void build_combined(const float* __restrict__ bf, const float* __restrict__ cx,
                               const int* __restrict__ map, float* __restrict__ comb)
{
    long long i = (long long)blockIdx.x * blockDim.x + threadIdx.x;
    if (i >= (long long)NB * 192) return;
    int n = (int)(i / 192), c = (int)(i % 192);
    comb[i] = (c < 64) ? bf[(long long)n * 64 + c]
                       : cx[(long long)map[n] * 128 + (c - 64)];
}

// fa_w1 (8,192,128) -> [192, 1024] with col = h*128 + j
__global__ void transpose_faw1(const float* __restrict__ w, float* __restrict__ out)
{
    int i = blockIdx.x * blockDim.x + threadIdx.x;
    if (i >= 8 * 192 * 128) return;
    int h = i / (192 * 128), r = (i / 128) % 192, j = i % 128;
    out[r * 1024 + h * 128 + j] = w[i];
}

__global__ void fa_out(const float* __restrict__ fah, const float* __restrict__ w2,
                       const float* __restrict__ b2, float* __restrict__ wmean)
{
    long long n = ((long long)blockIdx.x * blockDim.x + threadIdx.x) >> 5;
    int lane = threadIdx.x & 31;
    if (n >= NB) return;
    float m0 = 0.0f, m1 = 0.0f;
    for (int h = 0; h < 8; h++) {
        const float* ph = fah + n * 1024 + h * 128;
        const float* pw = w2 + h * 256;
        float s0 = 0.0f, s1 = 0.0f;
        for (int k = lane; k < 128; k += 32) {
            float v = ph[k];
            s0 += v * pw[k * 2 + 0];
            s1 += v * pw[k * 2 + 1];
        }
        #pragma unroll
        for (int o = 16; o; o >>= 1) {
            s0 += __shfl_down_sync(0xffffffffu, s0, o);
            s1 += __shfl_down_sync(0xffffffffu, s1, o);
        }
        if (lane == 0) {
            s0 += b2[h * 2]; s1 += b2[h * 2 + 1];
            float mx = fmaxf(s0, s1);
            float e0 = expf(s0 - mx), e1 = expf(s1 - mx);
            float inv = 1.0f / (e0 + e1);
            m0 += e0 * inv; m1 += e1 * inv;
        }
    }
    if (lane == 0) {
        wmean[n * 2 + 0] = m0 * 0.125f;
        wmean[n * 2 + 1] = m1 * 0.125f;
    }
}

__global__ void fuse_k(float* __restrict__ comb, const float* __restrict__ wmean)
{
    long long i = (long long)blockIdx.x * blockDim.x + threadIdx.x;
    if (i >= (long long)NB * 192) return;
    int n = (int)(i / 192), c = (int)(i % 192);
    comb[i] *= (c < 64) ? wmean[n * 2] : wmean[n * 2 + 1];
}

__global__ void small_xform(const float* __restrict__ x, const float* __restrict__ wl,
                            const float* __restrict__ wr, float* __restrict__ xl,
                            float* __restrict__ xr, int N, int K)
{
    int n = blockIdx.x * blockDim.x + threadIdx.x;
    if (n >= N) return;
    float a0 = 0, a1 = 0, b0 = 0, b1 = 0;
    const float* px = x + (long long)n * K;
    for (int k = 0; k < K; k++) {
        float v = px[k];
        a0 += v * wl[k * 2]; a1 += v * wl[k * 2 + 1];
        b0 += v * wr[k * 2]; b1 += v * wr[k * 2 + 1];
    }
    xl[n * 2] = a0; xl[n * 2 + 1] = a1;
    xr[n * 2] = b0; xr[n * 2 + 1] = b1;
}

__global__ void final_lsm(const float* __restrict__ agg, const float* __restrict__ b,
                          float* __restrict__ out, int N)
{
    int n = blockIdx.x * blockDim.x + threadIdx.x;
    if (n >= N) return;
    float v0 = agg[n * 2] + b[0], v1 = agg[n * 2 + 1] + b[1];
    float mx = fmaxf(v0, v1);
    float lse = mx + logf(expf(v0 - mx) + expf(v1 - mx));
    out[n * 2] = v0 - lse;
    out[n * 2 + 1] = v1 - lse;
}

// ---------------------------------------------------------------------------
static inline int cdivll(long long a, long long b) { return (int)((a + b - 1) / b); }

static void fill(float* p, float v, long long n) {
    fillk<<<cdivll(n, 256), 256>>>(p, v, n);
}

static void gemm(const float* A, const float* B, float* C, const float* bias,
                 int N, int K, int M, int relu)
{
    dim3 grid(M / MM_BN, (N + MM_BM - 1) / MM_BM);
    tf32gemm<<<grid, 256>>>(A, B, C, bias, N, K, M, relu);
}

template<int LPG, int D>
static void run_gat_edges(const int* ei, int E_real, int Nnodes, int H,
                          const float* xl, const float* xr, const float* att,
                          float* p, float* smax, float* ssum, float* agg)
{
    int E_tot = E_real + Nnodes;
    fill(smax, -INFINITY, (long long)Nnodes * H);
    fill(ssum, 0.0f, (long long)Nnodes * H);
    fill(agg, 0.0f, (long long)Nnodes * H * D);
    long long ngroups = (long long)E_tot * H;
    edge_logits_t<LPG, D><<<cdivll(ngroups * LPG, 256), 256>>>(ei, E_real, ngroups, xl, xr, att, p, smax, H);
    edge_exp<<<cdivll(ngroups, 256), 256>>>(ei, E_real, ngroups, p, smax, ssum, H);
    edge_agg_t<LPG, D><<<cdivll(ngroups * LPG, 256), 256>>>(ei, E_real, ngroups, p, ssum, xl, agg, H);
}

extern "C" void kernel_launch(void* const* d_in, const int* in_sizes, int n_in,
                              void* d_out, int out_size)
{
    int idx_bf = 0, idx_cf = 1, idx_bei, idx_cei, idx_map, base_w;
    if (in_sizes[2] == 2 * EB) { idx_bei = 2; idx_cei = 3; idx_map = 4; base_w = 5; }
    else                       { base_w = 2; idx_bei = 26; idx_cei = 27; idx_map = 28; }
    const float* bf  = (const float*)d_in[idx_bf];
    const float* cf  = (const float*)d_in[idx_cf];
    const int*   bei = (const int*)d_in[idx_bei];
    const int*   cei = (const int*)d_in[idx_cei];
    const int*   b2c = (const int*)d_in[idx_map];

    enum { C1WL, C1WR, C1ATT, C1B, C2WL, C2WR, C2ATT, C2B,
           FAW1, FAB1, FAW2, FAB2,
           B1WL, B1WR, B1ATT, B1B, B2WL, B2WR, B2ATT, B2B,
           B3WL, B3WR, B3ATT, B3B };
    const float* W[24];
    for (int i = 0; i < 24; i++) W[i] = (const float*)d_in[base_w + i];

    float* S;
    cudaGetSymbolAddress((void**)&S, g_scratch);

    float* c_xl  = S + O_CXL;   float* c_xr  = S + O_CXR;
    float* c_h1  = S + O_CH1;   float* c_agg = S + O_CAGG;
    float* c_xl2 = S + O_CXL2;  float* c_xr2 = S + O_CXR2;
    float* c_h2  = S + O_CH2;   float* ce_p  = S + O_CEP;
    float* c_max = S + O_CMAX;  float* c_sum = S + O_CSUM;
    float* comb  = S + O_COMB;  float* fah   = S + O_FAH;
    float* wmean = S + O_WM;    float* faW   = S + O_FAW;
    float* b_xl  = S + O_BXL;   float* b_xr  = S + O_BXR;
    float* b_agg = S + O_BAGG;  float* b_h1  = S + O_BH1;
    float* b_h2  = S + O_BH2;   float* be_p  = S + O_BEP;
    float* b_max = S + O_BMAX;  float* b_sum = S + O_BSUM;
    float* xl3   = S + O_XL3;   float* xr3   = S + O_XR3;
    float* agg3  = S + O_AGG3;

    // ---- Community GNN ----
    gemm(cf, W[C1WL], c_xl, nullptr, NC, 32, 512, 0);
    gemm(cf, W[C1WR], c_xr, nullptr, NC, 32, 512, 0);
    run_gat_edges<32, 64>(cei, EC, NC, 8, c_xl, c_xr, W[C1ATT], ce_p, c_max, c_sum, c_agg);
    bias_relu_k<<<cdivll((long long)NC * 512, 256), 256>>>(c_agg, W[C1B], c_h1, (long long)NC * 512, 512);

    gemm(c_h1, W[C2WL], c_xl2, nullptr, NC, 512, 128, 0);
    gemm(c_h1, W[C2WR], c_xr2, nullptr, NC, 512, 128, 0);
    run_gat_edges<16, 32>(cei, EC, NC, 4, c_xl2, c_xr2, W[C2ATT], ce_p, c_max, c_sum, c_agg);
    bias_relu_k<<<cdivll((long long)NC * 128, 256), 256>>>(c_agg, W[C2B], c_h2, (long long)NC * 128, 128);

    // ---- Feature-attention fusion ----
    build_combined<<<cdivll((long long)NB * 192, 256), 256>>>(bf, c_h2, b2c, comb);
    transpose_faw1<<<cdivll(8 * 192 * 128, 256), 256>>>(W[FAW1], faW);
    gemm(comb, faW, fah, W[FAB1], NB, 192, 1024, 1);
    fa_out<<<cdivll((long long)NB * 32, 256), 256>>>(fah, W[FAW2], W[FAB2], wmean);
    fuse_k<<<cdivll((long long)NB * 192, 256), 256>>>(comb, wmean);

    // ---- Building GNN ----
    gemm(comb, W[B1WL], b_xl, nullptr, NB, 192, 512, 0);
    gemm(comb, W[B1WR], b_xr, nullptr, NB, 192, 512, 0);
    run_gat_edges<32, 64>(bei, EB, NB, 8, b_xl, b_xr, W[B1ATT], be_p, b_max, b_sum, b_agg);
    bias_relu_k<<<cdivll((long long)NB * 512, 256), 256>>>(b_agg, W[B1B], b_h1, (long long)NB * 512, 512);

    gemm(b_h1, W[B2WL], b_xl, nullptr, NB, 512, 128, 0);
    gemm(b_h1, W[B2WR], b_xr, nullptr, NB, 512, 128, 0);
    run_gat_edges<16, 32>(bei, EB, NB, 4, b_xl, b_xr, W[B2ATT], be_p, b_max, b_sum, b_agg);
    bias_relu_k<<<cdivll((long long)NB * 128, 256), 256>>>(b_agg, W[B2B], b_h2, (long long)NB * 128, 128);

    small_xform<<<cdivll(NB, 256), 256>>>(b_h2, W[B3WL], W[B3WR], xl3, xr3, NB, 128);
    run_gat_edges<2, 2>(bei, EB, NB, 1, xl3, xr3, W[B3ATT], be_p, b_max, b_sum, agg3);
    final_lsm<<<cdivll(NB, 256), 256>>>(agg3, W[B3B], (float*)d_out, NB);
}

// round 6
// speedup vs baseline: 3.8918x; 1.8069x over previous
#include <cuda_runtime.h>
#include <math.h>
#include <stdint.h>

// Problem constants
#define NB 100000
#define NC 10000
#define EB 400000
#define EC 80000
#define CAP 64

// ---------------------------------------------------------------------------
// Scratch layout (floats; int regions reinterpreted)
// ---------------------------------------------------------------------------
constexpr long long O_CXL  = 0;
constexpr long long O_CXR  = O_CXL  + (long long)NC * 512;
constexpr long long O_CH1  = O_CXR  + (long long)NC * 512;
constexpr long long O_CXL2 = O_CH1  + (long long)NC * 512;
constexpr long long O_CXR2 = O_CXL2 + (long long)NC * 128;
constexpr long long O_CH2  = O_CXR2 + (long long)NC * 128;
constexpr long long O_COMB = O_CH2  + (long long)NC * 128;
constexpr long long O_FAH  = O_COMB + (long long)NB * 192;
constexpr long long O_WM   = O_FAH  + (long long)NB * 1024;
constexpr long long O_FAW  = O_WM   + (long long)NB * 2;
constexpr long long O_BXL  = O_FAW  + (long long)192 * 1024;
constexpr long long O_BXR  = O_BXL  + (long long)NB * 512;
constexpr long long O_BH1  = O_BXR  + (long long)NB * 512;
constexpr long long O_BH2  = O_BH1  + (long long)NB * 512;
constexpr long long O_XL3  = O_BH2  + (long long)NB * 128;
constexpr long long O_XR3  = O_XL3  + (long long)NB * 2;
constexpr long long O_BCNT = O_XR3  + (long long)NB * 2;         // int
constexpr long long O_BEL  = O_BCNT + (long long)NB;             // int
constexpr long long O_CCNT = O_BEL  + (long long)NB * CAP;       // int
constexpr long long O_CEL  = O_CCNT + (long long)NC;             // int
constexpr long long SCRATCH_TOTAL = O_CEL + (long long)NC * CAP;

__device__ float g_scratch[SCRATCH_TOTAL];

// ---------------------------------------------------------------------------
// CSR-ish bucket build
// ---------------------------------------------------------------------------
__global__ void izero(int* __restrict__ p, int n) {
    int i = blockIdx.x * blockDim.x + threadIdx.x;
    if (i < n) p[i] = 0;
}

__global__ void build_lists(const int* __restrict__ ei, int E,
                            int* __restrict__ cnt, int* __restrict__ el)
{
    int e = blockIdx.x * blockDim.x + threadIdx.x;
    if (e >= E) return;
    int d = ei[E + e];                    // dst
    int slot = atomicAdd(&cnt[d], 1);
    if (slot < CAP) el[(long long)d * CAP + slot] = e;
}

// ---------------------------------------------------------------------------
// TF32 tensor-core GEMM with cp.async double buffering.
// C[N,M] = A[N,K] @ B[K,M] (+bias, optional relu)
// 128x128x32 CTA tile, 8 warps, warp tile 64x32, mma.m16n8k8.tf32.
// Requires: K % 32 == 0, M % 128 == 0.
// ---------------------------------------------------------------------------
#define AS_STRIDE 36
#define BS_STRIDE 132
#define ABUF (128 * AS_STRIDE)            // 4608 floats
#define BBUF (32 * BS_STRIDE)             // 4224 floats
#define BUFSZ (ABUF + BBUF)               // 8832 floats
#define GEMM_SMEM_BYTES (2 * BUFSZ * 4)   // 70656 bytes

__device__ __forceinline__ void cp16(uint32_t d, const void* s, bool pred) {
    int sz = pred ? 16 : 0;
    asm volatile("cp.async.ca.shared.global [%0], [%1], 16, %2;\n"
                 :: "r"(d), "l"(s), "r"(sz));
}

__device__ __forceinline__ void mma_tf32(float* c, unsigned a0, unsigned a1,
                                         unsigned a2, unsigned a3,
                                         unsigned b0, unsigned b1) {
    asm volatile(
        "mma.sync.aligned.m16n8k8.row.col.f32.tf32.tf32.f32 "
        "{%0,%1,%2,%3},{%4,%5,%6,%7},{%8,%9},{%0,%1,%2,%3};"
        : "+f"(c[0]), "+f"(c[1]), "+f"(c[2]), "+f"(c[3])
        : "r"(a0), "r"(a1), "r"(a2), "r"(a3), "r"(b0), "r"(b1));
}

__global__ void __launch_bounds__(256, 2) tf32gemm(
    const float* __restrict__ A, const float* __restrict__ B,
    float* __restrict__ C, const float* __restrict__ bias,
    int N, int K, int M, int relu)
{
    extern __shared__ float sm[];
    int tid = threadIdx.x;
    int warp = tid >> 5, lane = tid & 31;
    int wm = (warp >> 2) * 64;
    int wn = (warp & 3) * 32;
    int g  = lane >> 2;
    int tg = lane & 3;
    int rowBase = blockIdx.y * 128;
    int colBase = blockIdx.x * 128;

    uint32_t sbase = (uint32_t)__cvta_generic_to_shared(sm);

    float acc[4][4][4] = {};
    int T = K >> 5;   // number of 32-wide k tiles

    // Issue one tile's loads into buffer buf
    auto issue_tile = [&](int k0, int buf) {
        uint32_t abase = sbase + (uint32_t)(buf * BUFSZ) * 4u;
        uint32_t bbase = abase + (uint32_t)ABUF * 4u;
        #pragma unroll
        for (int it = 0; it < 4; it++) {
            int chunk = tid + it * 256;
            // A: 128 rows x 32 floats, 8 chunks/row
            int r  = chunk >> 3;
            int kc = (chunk & 7) << 2;
            int gr = rowBase + r;
            bool pa = gr < N;
            const float* srcA = A + (long long)(pa ? gr : 0) * K + k0 + kc;
            cp16(abase + (uint32_t)(r * AS_STRIDE + kc) * 4u, srcA, pa);
            // B: 32 rows(k) x 128 floats, 32 chunks/row
            int kk = chunk >> 5;
            int nn = (chunk & 31) << 2;
            const float* srcB = B + (long long)(k0 + kk) * M + colBase + nn;
            cp16(bbase + (uint32_t)(kk * BS_STRIDE + nn) * 4u, srcB, true);
        }
        asm volatile("cp.async.commit_group;\n");
    };

    issue_tile(0, 0);
    for (int t = 0; t < T; t++) {
        if (t + 1 < T) {
            issue_tile((t + 1) << 5, (t + 1) & 1);
            asm volatile("cp.async.wait_group 1;\n");
        } else {
            asm volatile("cp.async.wait_group 0;\n");
        }
        __syncthreads();

        const float* as = sm + (t & 1) * BUFSZ;
        const float* bs = as + ABUF;
        #pragma unroll
        for (int ks = 0; ks < 32; ks += 8) {
            unsigned af[4][4], bf[4][2];
            #pragma unroll
            for (int mi = 0; mi < 4; mi++) {
                int m = wm + mi * 16 + g;
                af[mi][0] = __float_as_uint(as[m * AS_STRIDE + ks + tg]);
                af[mi][1] = __float_as_uint(as[(m + 8) * AS_STRIDE + ks + tg]);
                af[mi][2] = __float_as_uint(as[m * AS_STRIDE + ks + tg + 4]);
                af[mi][3] = __float_as_uint(as[(m + 8) * AS_STRIDE + ks + tg + 4]);
            }
            #pragma unroll
            for (int nj = 0; nj < 4; nj++) {
                int n = wn + nj * 8 + g;
                bf[nj][0] = __float_as_uint(bs[(ks + tg) * BS_STRIDE + n]);
                bf[nj][1] = __float_as_uint(bs[(ks + tg + 4) * BS_STRIDE + n]);
            }
            #pragma unroll
            for (int mi = 0; mi < 4; mi++)
                #pragma unroll
                for (int nj = 0; nj < 4; nj++)
                    mma_tf32(acc[mi][nj], af[mi][0], af[mi][1], af[mi][2], af[mi][3],
                             bf[nj][0], bf[nj][1]);
        }
        __syncthreads();
    }

    #pragma unroll
    for (int mi = 0; mi < 4; mi++) {
        #pragma unroll
        for (int nj = 0; nj < 4; nj++) {
            int row = rowBase + wm + mi * 16 + g;
            int col = colBase + wn + nj * 8 + tg * 2;
            float b0 = 0.f, b1 = 0.f;
            if (bias) { b0 = bias[col]; b1 = bias[col + 1]; }
            if (row < N) {
                float2 v = make_float2(acc[mi][nj][0] + b0, acc[mi][nj][1] + b1);
                if (relu) { v.x = fmaxf(v.x, 0.f); v.y = fmaxf(v.y, 0.f); }
                *(float2*)(C + (long long)row * M + col) = v;
            }
            if (row + 8 < N) {
                float2 v = make_float2(acc[mi][nj][2] + b0, acc[mi][nj][3] + b1);
                if (relu) { v.x = fmaxf(v.x, 0.f); v.y = fmaxf(v.y, 0.f); }
                *(float2*)(C + (long long)(row + 8) * M + col) = v;
            }
        }
    }
}

// ---------------------------------------------------------------------------
// Fused GATv2 softmax+aggregate: one LPG-lane group per (dst, head).
// Pass 1: segment max (recompute logits). Pass 2: recompute, accumulate
// sum(p) and sum(p * xl[src]); epilogue: /sum, +bias, optional relu.
// Self-loop handled implicitly (i == c).
// ---------------------------------------------------------------------------
template<int LPG, int D, int H, bool RELU>
__global__ void gat_fused(const int* __restrict__ ei,
                          const int* __restrict__ cnt, const int* __restrict__ el,
                          const float* __restrict__ xl, const float* __restrict__ xr,
                          const float* __restrict__ att, const float* __restrict__ bias,
                          float* __restrict__ out, int Nnodes)
{
    constexpr int VPL = D / LPG;
    long long t = (long long)blockIdx.x * blockDim.x + threadIdx.x;
    long long gidx = t / LPG;
    int lane = (int)(t % LPG);
    if (gidx >= (long long)Nnodes * H) return;
    int dst = (int)(gidx / H), h = (int)(gidx % H);

    float xr_d[VPL], a_d[VPL];
    const float* pr = xr + ((long long)dst * H + h) * D;
    const float* pa = att + (long long)h * D;
    #pragma unroll
    for (int vi = 0; vi < VPL; vi++) {
        xr_d[vi] = pr[lane + vi * LPG];
        a_d[vi]  = pa[lane + vi * LPG];
    }
    int c = cnt[dst]; if (c > CAP) c = CAP;
    const int* lst = el + (long long)dst * CAP;

    // Pass 1: max logit
    float mx = -1e30f;
    for (int i = 0; i <= c; i++) {
        int src = (i == c) ? dst : ei[lst[i]];
        const float* pl = xl + ((long long)src * H + h) * D;
        float s = 0.0f;
        #pragma unroll
        for (int vi = 0; vi < VPL; vi++) {
            float v = pl[lane + vi * LPG] + xr_d[vi];
            v = v > 0.0f ? v : 0.2f * v;
            s += v * a_d[vi];
        }
        #pragma unroll
        for (int o = LPG / 2; o; o >>= 1) s += __shfl_xor_sync(0xffffffffu, s, o, LPG);
        mx = fmaxf(mx, s);
    }

    // Pass 2: accumulate
    float acc[VPL];
    #pragma unroll
    for (int vi = 0; vi < VPL; vi++) acc[vi] = 0.0f;
    float wsum = 0.0f;
    for (int i = 0; i <= c; i++) {
        int src = (i == c) ? dst : ei[lst[i]];
        const float* pl = xl + ((long long)src * H + h) * D;
        float vals[VPL];
        float s = 0.0f;
        #pragma unroll
        for (int vi = 0; vi < VPL; vi++) {
            vals[vi] = pl[lane + vi * LPG];
            float v = vals[vi] + xr_d[vi];
            v = v > 0.0f ? v : 0.2f * v;
            s += v * a_d[vi];
        }
        #pragma unroll
        for (int o = LPG / 2; o; o >>= 1) s += __shfl_xor_sync(0xffffffffu, s, o, LPG);
        float p = expf(s - mx);
        wsum += p;
        #pragma unroll
        for (int vi = 0; vi < VPL; vi++) acc[vi] += p * vals[vi];
    }

    float inv = 1.0f / wsum;
    float* po = out + ((long long)dst * H + h) * D;
    #pragma unroll
    for (int vi = 0; vi < VPL; vi++) {
        float v = acc[vi] * inv + bias[h * D + lane + vi * LPG];
        if (RELU) v = fmaxf(v, 0.0f);
        po[lane + vi * LPG] = v;
    }
}

// Layer 3 (H=1, D=2) fused with final log-softmax, writes d_out.
__global__ void gat3_lsm(const int* __restrict__ ei,
                         const int* __restrict__ cnt, const int* __restrict__ el,
                         const float* __restrict__ xl, const float* __restrict__ xr,
                         const float* __restrict__ att, const float* __restrict__ bias,
                         float* __restrict__ out, int Nnodes)
{
    long long t = (long long)blockIdx.x * blockDim.x + threadIdx.x;
    long long gidx = t >> 1;
    int lane = (int)(t & 1);
    if (gidx >= Nnodes) return;
    int dst = (int)gidx;

    float xr_d = xr[(long long)dst * 2 + lane];
    float a_d  = att[lane];
    int c = cnt[dst]; if (c > CAP) c = CAP;
    const int* lst = el + (long long)dst * CAP;

    float mx = -1e30f;
    for (int i = 0; i <= c; i++) {
        int src = (i == c) ? dst : ei[lst[i]];
        float v = xl[(long long)src * 2 + lane] + xr_d;
        v = v > 0.0f ? v : 0.2f * v;
        float s = v * a_d;
        s += __shfl_xor_sync(0xffffffffu, s, 1, 2);
        mx = fmaxf(mx, s);
    }
    float acc = 0.0f, wsum = 0.0f;
    for (int i = 0; i <= c; i++) {
        int src = (i == c) ? dst : ei[lst[i]];
        float xv = xl[(long long)src * 2 + lane];
        float v = xv + xr_d;
        v = v > 0.0f ? v : 0.2f * v;
        float s = v * a_d;
        s += __shfl_xor_sync(0xffffffffu, s, 1, 2);
        float p = expf(s - mx);
        wsum += p;
        acc += p * xv;
    }
    float v = acc / wsum + bias[lane];
    float o = __shfl_xor_sync(0xffffffffu, v, 1, 2);
    float m2 = fmaxf(v, o);
    float lse = m2 + logf(expf(v - m2) + expf(o - m2));
    out[(long long)dst * 2 + lane] = v - lse;
}

// ---------------------------------------------------------------------------
// Misc kernels
// ---------------------------------------------------------------------------
__global__ void build_combined(const float* __restrict__ bf, const float* __restrict__ cx,
                               const int* __restrict__ map, float* __restrict__ comb)
{
    long long i = (long long)blockIdx.x * blockDim.x + threadIdx.x;
    if (i >= (long long)NB * 192) return;
    int n = (int)(i / 192), c = (int)(i % 192);
    comb[i] = (c < 64) ? bf[(long long)n * 64 + c]
                       : cx[(long long)map[n] * 128 + (c - 64)];
}

// fa_w1 (8,192,128) -> [192, 1024] with col = h*128 + j
__global__ void transpose_faw1(const float* __restrict__ w, float* __restrict__ out)
{
    int i = blockIdx.x * blockDim.x + threadIdx.x;
    if (i >= 8 * 192 * 128) return;
    int h = i / (192 * 128), r = (i / 128) % 192, j = i % 128;
    out[r * 1024 + h * 128 + j] = w[i];
}

__global__ void fa_out(const float* __restrict__ fah, const float* __restrict__ w2,
                       const float* __restrict__ b2, float* __restrict__ wmean)
{
    long long n = ((long long)blockIdx.x * blockDim.x + threadIdx.x) >> 5;
    int lane = threadIdx.x & 31;
    if (n >= NB) return;
    float m0 = 0.0f, m1 = 0.0f;
    for (int h = 0; h < 8; h++) {
        const float* ph = fah + n * 1024 + h * 128;
        const float* pw = w2 + h * 256;
        float s0 = 0.0f, s1 = 0.0f;
        for (int k = lane; k < 128; k += 32) {
            float v = ph[k];
            s0 += v * pw[k * 2 + 0];
            s1 += v * pw[k * 2 + 1];
        }
        #pragma unroll
        for (int o = 16; o; o >>= 1) {
            s0 += __shfl_down_sync(0xffffffffu, s0, o);
            s1 += __shfl_down_sync(0xffffffffu, s1, o);
        }
        if (lane == 0) {
            s0 += b2[h * 2]; s1 += b2[h * 2 + 1];
            float mx = fmaxf(s0, s1);
            float e0 = expf(s0 - mx), e1 = expf(s1 - mx);
            float inv = 1.0f / (e0 + e1);
            m0 += e0 * inv; m1 += e1 * inv;
        }
    }
    if (lane == 0) {
        wmean[n * 2 + 0] = m0 * 0.125f;
        wmean[n * 2 + 1] = m1 * 0.125f;
    }
}

__global__ void fuse_k(float* __restrict__ comb, const float* __restrict__ wmean)
{
    long long i = (long long)blockIdx.x * blockDim.x + threadIdx.x;
    if (i >= (long long)NB * 192) return;
    int n = (int)(i / 192), c = (int)(i % 192);
    comb[i] *= (c < 64) ? wmean[n * 2] : wmean[n * 2 + 1];
}

__global__ void small_xform(const float* __restrict__ x, const float* __restrict__ wl,
                            const float* __restrict__ wr, float* __restrict__ xl,
                            float* __restrict__ xr, int N, int K)
{
    int n = blockIdx.x * blockDim.x + threadIdx.x;
    if (n >= N) return;
    float a0 = 0, a1 = 0, b0 = 0, b1 = 0;
    const float* px = x + (long long)n * K;
    for (int k = 0; k < K; k++) {
        float v = px[k];
        a0 += v * wl[k * 2]; a1 += v * wl[k * 2 + 1];
        b0 += v * wr[k * 2]; b1 += v * wr[k * 2 + 1];
    }
    xl[n * 2] = a0; xl[n * 2 + 1] = a1;
    xr[n * 2] = b0; xr[n * 2 + 1] = b1;
}

// ---------------------------------------------------------------------------
static inline int cdivll(long long a, long long b) { return (int)((a + b - 1) / b); }

static void gemm(const float* A, const float* B, float* C, const float* bias,
                 int N, int K, int M, int relu)
{
    dim3 grid(M / 128, (N + 127) / 128);
    tf32gemm<<<grid, 256, GEMM_SMEM_BYTES>>>(A, B, C, bias, N, K, M, relu);
}

extern "C" void kernel_launch(void* const* d_in, const int* in_sizes, int n_in,
                              void* d_out, int out_size)
{
    int idx_bf = 0, idx_cf = 1, idx_bei, idx_cei, idx_map, base_w;
    if (in_sizes[2] == 2 * EB) { idx_bei = 2; idx_cei = 3; idx_map = 4; base_w = 5; }
    else                       { base_w = 2; idx_bei = 26; idx_cei = 27; idx_map = 28; }
    const float* bf  = (const float*)d_in[idx_bf];
    const float* cf  = (const float*)d_in[idx_cf];
    const int*   bei = (const int*)d_in[idx_bei];
    const int*   cei = (const int*)d_in[idx_cei];
    const int*   b2c = (const int*)d_in[idx_map];

    enum { C1WL, C1WR, C1ATT, C1B, C2WL, C2WR, C2ATT, C2B,
           FAW1, FAB1, FAW2, FAB2,
           B1WL, B1WR, B1ATT, B1B, B2WL, B2WR, B2ATT, B2B,
           B3WL, B3WR, B3ATT, B3B };
    const float* W[24];
    for (int i = 0; i < 24; i++) W[i] = (const float*)d_in[base_w + i];

    float* S;
    cudaGetSymbolAddress((void**)&S, g_scratch);
    cudaFuncSetAttribute(tf32gemm, cudaFuncAttributeMaxDynamicSharedMemorySize,
                         GEMM_SMEM_BYTES);

    float* c_xl  = S + O_CXL;   float* c_xr  = S + O_CXR;
    float* c_h1  = S + O_CH1;
    float* c_xl2 = S + O_CXL2;  float* c_xr2 = S + O_CXR2;
    float* c_h2  = S + O_CH2;
    float* comb  = S + O_COMB;  float* fah   = S + O_FAH;
    float* wmean = S + O_WM;    float* faW   = S + O_FAW;
    float* b_xl  = S + O_BXL;   float* b_xr  = S + O_BXR;
    float* b_h1  = S + O_BH1;   float* b_h2  = S + O_BH2;
    float* xl3   = S + O_XL3;   float* xr3   = S + O_XR3;
    int* bcnt = (int*)(S + O_BCNT);
    int* bel  = (int*)(S + O_BEL);
    int* ccnt = (int*)(S + O_CCNT);
    int* cel  = (int*)(S + O_CEL);

    // ---- Build per-dst edge lists (once per graph, reused across layers) ----
    izero<<<cdivll(NB, 256), 256>>>(bcnt, NB);
    izero<<<cdivll(NC, 256), 256>>>(ccnt, NC);
    build_lists<<<cdivll(EB, 256), 256>>>(bei, EB, bcnt, bel);
    build_lists<<<cdivll(EC, 256), 256>>>(cei, EC, ccnt, cel);

    // ---- Community GNN ----
    gemm(cf, W[C1WL], c_xl, nullptr, NC, 32, 512, 0);
    gemm(cf, W[C1WR], c_xr, nullptr, NC, 32, 512, 0);
    gat_fused<32, 64, 8, true><<<cdivll((long long)NC * 8 * 32, 256), 256>>>(
        cei, ccnt, cel, c_xl, c_xr, W[C1ATT], W[C1B], c_h1, NC);

    gemm(c_h1, W[C2WL], c_xl2, nullptr, NC, 512, 128, 0);
    gemm(c_h1, W[C2WR], c_xr2, nullptr, NC, 512, 128, 0);
    gat_fused<16, 32, 4, true><<<cdivll((long long)NC * 4 * 16, 256), 256>>>(
        cei, ccnt, cel, c_xl2, c_xr2, W[C2ATT], W[C2B], c_h2, NC);

    // ---- Feature-attention fusion ----
    build_combined<<<cdivll((long long)NB * 192, 256), 256>>>(bf, c_h2, b2c, comb);
    transpose_faw1<<<cdivll(8 * 192 * 128, 256), 256>>>(W[FAW1], faW);
    gemm(comb, faW, fah, W[FAB1], NB, 192, 1024, 1);
    fa_out<<<cdivll((long long)NB * 32, 256), 256>>>(fah, W[FAW2], W[FAB2], wmean);
    fuse_k<<<cdivll((long long)NB * 192, 256), 256>>>(comb, wmean);

    // ---- Building GNN ----
    gemm(comb, W[B1WL], b_xl, nullptr, NB, 192, 512, 0);
    gemm(comb, W[B1WR], b_xr, nullptr, NB, 192, 512, 0);
    gat_fused<32, 64, 8, true><<<cdivll((long long)NB * 8 * 32, 256), 256>>>(
        bei, bcnt, bel, b_xl, b_xr, W[B1ATT], W[B1B], b_h1, NB);

    gemm(b_h1, W[B2WL], b_xl, nullptr, NB, 512, 128, 0);
    gemm(b_h1, W[B2WR], b_xr, nullptr, NB, 512, 128, 0);
    gat_fused<16, 32, 4, true><<<cdivll((long long)NB * 4 * 16, 256), 256>>>(
        bei, bcnt, bel, b_xl, b_xr, W[B2ATT], W[B2B], b_h2, NB);

    small_xform<<<cdivll(NB, 256), 256>>>(b_h2, W[B3WL], W[B3WR], xl3, xr3, NB, 128);
    gat3_lsm<<<cdivll((long long)NB * 2, 256), 256>>>(
        bei, bcnt, bel, xl3, xr3, W[B3ATT], W[B3B], (float*)d_out, NB);
}

// round 7
// speedup vs baseline: 5.3055x; 1.3633x over previous
#include <cuda_runtime.h>
#include <math.h>
#include <stdint.h>

// Problem constants
#define NB 100000
#define NC 10000
#define EB 400000
#define EC 80000
#define CAP 64

// ---------------------------------------------------------------------------
// Scratch layout (floats; int regions reinterpreted)
// ---------------------------------------------------------------------------
constexpr long long O_CXLR = 0;                                   // [NC,1024]
constexpr long long O_CH1  = O_CXLR + (long long)NC * 1024;       // [NC,512]
constexpr long long O_CXLR2= O_CH1  + (long long)NC * 512;        // [NC,256]
constexpr long long O_CH2  = O_CXLR2+ (long long)NC * 256;        // [NC,128]
constexpr long long O_COMB = O_CH2  + (long long)NC * 128;        // [NB,192]
constexpr long long O_FAW  = O_COMB + (long long)NB * 192;        // [192,1024]
constexpr long long O_WM   = O_FAW  + (long long)192 * 1024;      // [NB,2]
constexpr long long O_WC1  = O_WM   + (long long)NB * 2;          // [32,1024]
constexpr long long O_WC2  = O_WC1  + (long long)32 * 1024;       // [512,256]
constexpr long long O_WB1  = O_WC2  + (long long)512 * 256;       // [192,1024]
constexpr long long O_WB2  = O_WB1  + (long long)192 * 1024;      // [512,256]
constexpr long long O_BXLR = O_WB2  + (long long)512 * 256;       // [NB,1024] (L2 reuses)
constexpr long long O_BH1  = O_BXLR + (long long)NB * 1024;       // [NB,512]
constexpr long long O_BH2  = O_BH1  + (long long)NB * 512;        // [NB,128]
constexpr long long O_XL3  = O_BH2  + (long long)NB * 128;        // [NB,2]
constexpr long long O_XR3  = O_XL3  + (long long)NB * 2;          // [NB,2]
constexpr long long O_BCNT = O_XR3  + (long long)NB * 2;          // int [NB]
constexpr long long O_BEL  = O_BCNT + (long long)NB;              // int [NB*CAP]
constexpr long long O_CCNT = O_BEL  + (long long)NB * CAP;        // int [NC]
constexpr long long O_CEL  = O_CCNT + (long long)NC;              // int [NC*CAP]
constexpr long long SCRATCH_TOTAL = O_CEL + (long long)NC * CAP;

__device__ float g_scratch[SCRATCH_TOTAL];

// ---------------------------------------------------------------------------
__global__ void fillk(float* __restrict__ x, float v, long long n) {
    long long i = (long long)blockIdx.x * blockDim.x + threadIdx.x;
    if (i < n) x[i] = v;
}

__global__ void izero(int* __restrict__ p, int n) {
    int i = blockIdx.x * blockDim.x + threadIdx.x;
    if (i < n) p[i] = 0;
}

// Bucket lists store SRC node ids directly (no edge-id indirection).
__global__ void build_lists(const int* __restrict__ ei, int E,
                            int* __restrict__ cnt, int* __restrict__ el)
{
    int e = blockIdx.x * blockDim.x + threadIdx.x;
    if (e >= E) return;
    int s = ei[e];
    int d = ei[E + e];
    int slot = atomicAdd(&cnt[d], 1);
    if (slot < CAP) el[(long long)d * CAP + slot] = s;
}

// out[k][0..M-1] = a[k][...], out[k][M..2M-1] = b[k][...]
__global__ void concat2(const float* __restrict__ a, const float* __restrict__ b,
                        float* __restrict__ out, int K, int M)
{
    int i = blockIdx.x * blockDim.x + threadIdx.x;
    if (i >= K * 2 * M) return;
    int k = i / (2 * M), c = i % (2 * M);
    out[i] = (c < M) ? a[k * M + c] : b[k * M + (c - M)];
}

// fa_w1 (8,192,128) -> [192, 1024] with col = h*128 + j
__global__ void transpose_faw1(const float* __restrict__ w, float* __restrict__ out)
{
    int i = blockIdx.x * blockDim.x + threadIdx.x;
    if (i >= 8 * 192 * 128) return;
    int h = i / (192 * 128), r = (i / 128) % 192, j = i % 128;
    out[r * 1024 + h * 128 + j] = w[i];
}

// ---------------------------------------------------------------------------
// TF32 tensor-core GEMM with cp.async double buffering.
// C[N,M] = A[N,K] @ B[K,M] (+bias, optional relu)
// 128x128x32 CTA tile, 8 warps, warp tile 64x32, mma.m16n8k8.tf32.
// Requires: K % 32 == 0, M % 128 == 0.
// fa mode (w2 != null): instead of storing C, reduce per-head MLP output:
//   per row: s = sum_j relu(acc+bias)[j] * w2[head][j][:], softmax(s+b2),
//   atomicAdd 0.125*softmax into wmean[row]. Head = blockIdx.x (128 cols).
// ---------------------------------------------------------------------------
#define AS_STRIDE 36
#define BS_STRIDE 132
#define ABUF (128 * AS_STRIDE)
#define BBUF (32 * BS_STRIDE)
#define BUFSZ (ABUF + BBUF)
#define GEMM_SMEM_BYTES (2 * BUFSZ * 4)

__device__ __forceinline__ void cp16(uint32_t d, const void* s, bool pred) {
    int sz = pred ? 16 : 0;
    asm volatile("cp.async.ca.shared.global [%0], [%1], 16, %2;\n"
                 :: "r"(d), "l"(s), "r"(sz));
}

__device__ __forceinline__ void mma_tf32(float* c, unsigned a0, unsigned a1,
                                         unsigned a2, unsigned a3,
                                         unsigned b0, unsigned b1) {
    asm volatile(
        "mma.sync.aligned.m16n8k8.row.col.f32.tf32.tf32.f32 "
        "{%0,%1,%2,%3},{%4,%5,%6,%7},{%8,%9},{%0,%1,%2,%3};"
        : "+f"(c[0]), "+f"(c[1]), "+f"(c[2]), "+f"(c[3])
        : "r"(a0), "r"(a1), "r"(a2), "r"(a3), "r"(b0), "r"(b1));
}

__global__ void __launch_bounds__(256, 2) tf32gemm(
    const float* __restrict__ A, const float* __restrict__ B,
    float* __restrict__ C, const float* __restrict__ bias,
    int N, int K, int M, int relu,
    const float* __restrict__ w2, const float* __restrict__ b2,
    float* __restrict__ wmean)
{
    extern __shared__ float sm[];
    int tid = threadIdx.x;
    int warp = tid >> 5, lane = tid & 31;
    int wm = (warp >> 2) * 64;
    int wn = (warp & 3) * 32;
    int g  = lane >> 2;
    int tg = lane & 3;
    int rowBase = blockIdx.y * 128;
    int colBase = blockIdx.x * 128;

    uint32_t sbase = (uint32_t)__cvta_generic_to_shared(sm);

    float acc[4][4][4] = {};
    int T = K >> 5;

    auto issue_tile = [&](int k0, int buf) {
        uint32_t abase = sbase + (uint32_t)(buf * BUFSZ) * 4u;
        uint32_t bbase = abase + (uint32_t)ABUF * 4u;
        #pragma unroll
        for (int it = 0; it < 4; it++) {
            int chunk = tid + it * 256;
            int r  = chunk >> 3;
            int kc = (chunk & 7) << 2;
            int gr = rowBase + r;
            bool pa = gr < N;
            const float* srcA = A + (long long)(pa ? gr : 0) * K + k0 + kc;
            cp16(abase + (uint32_t)(r * AS_STRIDE + kc) * 4u, srcA, pa);
            int kk = chunk >> 5;
            int nn = (chunk & 31) << 2;
            const float* srcB = B + (long long)(k0 + kk) * M + colBase + nn;
            cp16(bbase + (uint32_t)(kk * BS_STRIDE + nn) * 4u, srcB, true);
        }
        asm volatile("cp.async.commit_group;\n");
    };

    issue_tile(0, 0);
    for (int t = 0; t < T; t++) {
        if (t + 1 < T) {
            issue_tile((t + 1) << 5, (t + 1) & 1);
            asm volatile("cp.async.wait_group 1;\n");
        } else {
            asm volatile("cp.async.wait_group 0;\n");
        }
        __syncthreads();

        const float* as = sm + (t & 1) * BUFSZ;
        const float* bs = as + ABUF;
        #pragma unroll
        for (int ks = 0; ks < 32; ks += 8) {
            unsigned af[4][4], bf[4][2];
            #pragma unroll
            for (int mi = 0; mi < 4; mi++) {
                int m = wm + mi * 16 + g;
                af[mi][0] = __float_as_uint(as[m * AS_STRIDE + ks + tg]);
                af[mi][1] = __float_as_uint(as[(m + 8) * AS_STRIDE + ks + tg]);
                af[mi][2] = __float_as_uint(as[m * AS_STRIDE + ks + tg + 4]);
                af[mi][3] = __float_as_uint(as[(m + 8) * AS_STRIDE + ks + tg + 4]);
            }
            #pragma unroll
            for (int nj = 0; nj < 4; nj++) {
                int n = wn + nj * 8 + g;
                bf[nj][0] = __float_as_uint(bs[(ks + tg) * BS_STRIDE + n]);
                bf[nj][1] = __float_as_uint(bs[(ks + tg + 4) * BS_STRIDE + n]);
            }
            #pragma unroll
            for (int mi = 0; mi < 4; mi++)
                #pragma unroll
                for (int nj = 0; nj < 4; nj++)
                    mma_tf32(acc[mi][nj], af[mi][0], af[mi][1], af[mi][2], af[mi][3],
                             bf[nj][0], bf[nj][1]);
        }
        __syncthreads();
    }

    if (w2 == nullptr) {
        #pragma unroll
        for (int mi = 0; mi < 4; mi++) {
            #pragma unroll
            for (int nj = 0; nj < 4; nj++) {
                int row = rowBase + wm + mi * 16 + g;
                int col = colBase + wn + nj * 8 + tg * 2;
                float b0 = 0.f, b1 = 0.f;
                if (bias) { b0 = bias[col]; b1 = bias[col + 1]; }
                if (row < N) {
                    float2 v = make_float2(acc[mi][nj][0] + b0, acc[mi][nj][1] + b1);
                    if (relu) { v.x = fmaxf(v.x, 0.f); v.y = fmaxf(v.y, 0.f); }
                    *(float2*)(C + (long long)row * M + col) = v;
                }
                if (row + 8 < N) {
                    float2 v = make_float2(acc[mi][nj][2] + b0, acc[mi][nj][3] + b1);
                    if (relu) { v.x = fmaxf(v.x, 0.f); v.y = fmaxf(v.y, 0.f); }
                    *(float2*)(C + (long long)(row + 8) * M + col) = v;
                }
            }
        }
    } else {
        // fa-head epilogue. head = blockIdx.x; 128 rows of this CTA tile.
        int h = blockIdx.x;
        float* srow = sm;           // [128][2] partial logits
        for (int i = tid; i < 256; i += 256) srow[i] = 0.0f;
        __syncthreads();

        #pragma unroll
        for (int mi = 0; mi < 4; mi++) {
            float p0a = 0.f, p1a = 0.f;   // row wm+mi*16+g
            float p0b = 0.f, p1b = 0.f;   // row +8
            #pragma unroll
            for (int nj = 0; nj < 4; nj++) {
                int col_rel = wn + nj * 8 + tg * 2;
                float bb0 = bias[colBase + col_rel];
                float bb1 = bias[colBase + col_rel + 1];
                float2 wa = *(const float2*)(w2 + h * 256 + col_rel * 2);
                float2 wb = *(const float2*)(w2 + h * 256 + (col_rel + 1) * 2);
                float v0 = fmaxf(acc[mi][nj][0] + bb0, 0.f);
                float v1 = fmaxf(acc[mi][nj][1] + bb1, 0.f);
                p0a += v0 * wa.x + v1 * wb.x;
                p1a += v0 * wa.y + v1 * wb.y;
                float u0 = fmaxf(acc[mi][nj][2] + bb0, 0.f);
                float u1 = fmaxf(acc[mi][nj][3] + bb1, 0.f);
                p0b += u0 * wa.x + u1 * wb.x;
                p1b += u0 * wa.y + u1 * wb.y;
            }
            int ra = wm + mi * 16 + g;
            atomicAdd(&srow[ra * 2 + 0], p0a);
            atomicAdd(&srow[ra * 2 + 1], p1a);
            atomicAdd(&srow[(ra + 8) * 2 + 0], p0b);
            atomicAdd(&srow[(ra + 8) * 2 + 1], p1b);
        }
        __syncthreads();
        if (tid < 128) {
            int grow = rowBase + tid;
            if (grow < N) {
                float s0 = srow[tid * 2 + 0] + b2[h * 2 + 0];
                float s1 = srow[tid * 2 + 1] + b2[h * 2 + 1];
                float mx = fmaxf(s0, s1);
                float e0 = expf(s0 - mx), e1 = expf(s1 - mx);
                float inv = 0.125f / (e0 + e1);
                atomicAdd(&wmean[(long long)grow * 2 + 0], e0 * inv);
                atomicAdd(&wmean[(long long)grow * 2 + 1], e1 * inv);
            }
        }
    }
}

// ---------------------------------------------------------------------------
// Fused GATv2 softmax+aggregate, single-pass online softmax.
// One LPG-lane group per (dst, head). xl/xr packed rows with stride LDX.
// ---------------------------------------------------------------------------
template<int LPG, int D, int H, bool RELU>
__global__ void gat_fused(const int* __restrict__ cnt, const int* __restrict__ el,
                          const float* __restrict__ xl, const float* __restrict__ xr,
                          int ldx,
                          const float* __restrict__ att, const float* __restrict__ bias,
                          float* __restrict__ out, int Nnodes)
{
    constexpr int VPL = D / LPG;
    long long t = (long long)blockIdx.x * blockDim.x + threadIdx.x;
    long long gidx = t / LPG;
    int lane = (int)(t % LPG);
    if (gidx >= (long long)Nnodes * H) return;
    int dst = (int)(gidx / H), h = (int)(gidx % H);

    float xr_d[VPL], a_d[VPL];
    const float* pr = xr + (long long)dst * ldx + h * D;
    const float* pa = att + (long long)h * D;
    #pragma unroll
    for (int vi = 0; vi < VPL; vi++) {
        xr_d[vi] = pr[lane + vi * LPG];
        a_d[vi]  = pa[lane + vi * LPG];
    }
    int c = cnt[dst]; if (c > CAP) c = CAP;
    const int* lst = el + (long long)dst * CAP;

    float mx = -1e30f, wsum = 0.0f;
    float acc[VPL];
    #pragma unroll
    for (int vi = 0; vi < VPL; vi++) acc[vi] = 0.0f;

    for (int i = 0; i <= c; i++) {
        int src = (i == c) ? dst : lst[i];
        const float* pl = xl + (long long)src * ldx + h * D;
        float vals[VPL];
        float s = 0.0f;
        #pragma unroll
        for (int vi = 0; vi < VPL; vi++) {
            vals[vi] = pl[lane + vi * LPG];
            float v = vals[vi] + xr_d[vi];
            v = v > 0.0f ? v : 0.2f * v;
            s += v * a_d[vi];
        }
        #pragma unroll
        for (int o = LPG / 2; o; o >>= 1) s += __shfl_xor_sync(0xffffffffu, s, o, LPG);
        if (s > mx) {
            float f = expf(mx - s);
            wsum *= f;
            #pragma unroll
            for (int vi = 0; vi < VPL; vi++) acc[vi] *= f;
            mx = s;
        }
        float p = expf(s - mx);
        wsum += p;
        #pragma unroll
        for (int vi = 0; vi < VPL; vi++) acc[vi] += p * vals[vi];
    }

    float inv = 1.0f / wsum;
    float* po = out + ((long long)dst * H + h) * D;
    #pragma unroll
    for (int vi = 0; vi < VPL; vi++) {
        float v = acc[vi] * inv + bias[h * D + lane + vi * LPG];
        if (RELU) v = fmaxf(v, 0.0f);
        po[lane + vi * LPG] = v;
    }
}

// Layer 3 (H=1, D=2) fused with final log-softmax, writes d_out.
__global__ void gat3_lsm(const int* __restrict__ cnt, const int* __restrict__ el,
                         const float* __restrict__ xl, const float* __restrict__ xr,
                         const float* __restrict__ att, const float* __restrict__ bias,
                         float* __restrict__ out, int Nnodes)
{
    long long t = (long long)blockIdx.x * blockDim.x + threadIdx.x;
    long long gidx = t >> 1;
    int lane = (int)(t & 1);
    if (gidx >= Nnodes) return;
    int dst = (int)gidx;

    float xr_d = xr[(long long)dst * 2 + lane];
    float a_d  = att[lane];
    int c = cnt[dst]; if (c > CAP) c = CAP;
    const int* lst = el + (long long)dst * CAP;

    float mx = -1e30f, wsum = 0.0f, acc = 0.0f;
    for (int i = 0; i <= c; i++) {
        int src = (i == c) ? dst : lst[i];
        float xv = xl[(long long)src * 2 + lane];
        float v = xv + xr_d;
        v = v > 0.0f ? v : 0.2f * v;
        float s = v * a_d;
        s += __shfl_xor_sync(0xffffffffu, s, 1, 2);
        if (s > mx) {
            float f = expf(mx - s);
            wsum *= f; acc *= f; mx = s;
        }
        float p = expf(s - mx);
        wsum += p;
        acc += p * xv;
    }
    float v = acc / wsum + bias[lane];
    float o = __shfl_xor_sync(0xffffffffu, v, 1, 2);
    float m2 = fmaxf(v, o);
    float lse = m2 + logf(expf(v - m2) + expf(o - m2));
    out[(long long)dst * 2 + lane] = v - lse;
}

// ---------------------------------------------------------------------------
// Misc
// ---------------------------------------------------------------------------
__global__ void build_combined(const float* __restrict__ bf, const float* __restrict__ cx,
                               const int* __restrict__ map, float* __restrict__ comb)
{
    long long i = (long long)blockIdx.x * blockDim.x + threadIdx.x;
    if (i >= (long long)NB * 192) return;
    int n = (int)(i / 192), c = (int)(i % 192);
    comb[i] = (c < 64) ? bf[(long long)n * 64 + c]
                       : cx[(long long)map[n] * 128 + (c - 64)];
}

__global__ void fuse_k(float* __restrict__ comb, const float* __restrict__ wmean)
{
    long long i = (long long)blockIdx.x * blockDim.x + threadIdx.x;
    if (i >= (long long)NB * 192) return;
    int n = (int)(i / 192), c = (int)(i % 192);
    comb[i] *= (c < 64) ? wmean[n * 2] : wmean[n * 2 + 1];
}

__global__ void small_xform(const float* __restrict__ x, const float* __restrict__ wl,
                            const float* __restrict__ wr, float* __restrict__ xl,
                            float* __restrict__ xr, int N, int K)
{
    int n = blockIdx.x * blockDim.x + threadIdx.x;
    if (n >= N) return;
    float a0 = 0, a1 = 0, b0 = 0, b1 = 0;
    const float* px = x + (long long)n * K;
    for (int k = 0; k < K; k++) {
        float v = px[k];
        a0 += v * wl[k * 2]; a1 += v * wl[k * 2 + 1];
        b0 += v * wr[k * 2]; b1 += v * wr[k * 2 + 1];
    }
    xl[n * 2] = a0; xl[n * 2 + 1] = a1;
    xr[n * 2] = b0; xr[n * 2 + 1] = b1;
}

// ---------------------------------------------------------------------------
static inline int cdivll(long long a, long long b) { return (int)((a + b - 1) / b); }

static void gemm(const float* A, const float* B, float* C, const float* bias,
                 int N, int K, int M, int relu,
                 const float* w2 = nullptr, const float* b2 = nullptr,
                 float* wmean = nullptr)
{
    dim3 grid(M / 128, (N + 127) / 128);
    tf32gemm<<<grid, 256, GEMM_SMEM_BYTES>>>(A, B, C, bias, N, K, M, relu, w2, b2, wmean);
}

extern "C" void kernel_launch(void* const* d_in, const int* in_sizes, int n_in,
                              void* d_out, int out_size)
{
    int idx_bf = 0, idx_cf = 1, idx_bei, idx_cei, idx_map, base_w;
    if (in_sizes[2] == 2 * EB) { idx_bei = 2; idx_cei = 3; idx_map = 4; base_w = 5; }
    else                       { base_w = 2; idx_bei = 26; idx_cei = 27; idx_map = 28; }
    const float* bf  = (const float*)d_in[idx_bf];
    const float* cf  = (const float*)d_in[idx_cf];
    const int*   bei = (const int*)d_in[idx_bei];
    const int*   cei = (const int*)d_in[idx_cei];
    const int*   b2c = (const int*)d_in[idx_map];

    enum { C1WL, C1WR, C1ATT, C1B, C2WL, C2WR, C2ATT, C2B,
           FAW1, FAB1, FAW2, FAB2,
           B1WL, B1WR, B1ATT, B1B, B2WL, B2WR, B2ATT, B2B,
           B3WL, B3WR, B3ATT, B3B };
    const float* W[24];
    for (int i = 0; i < 24; i++) W[i] = (const float*)d_in[base_w + i];

    float* S;
    cudaGetSymbolAddress((void**)&S, g_scratch);
    cudaFuncSetAttribute(tf32gemm, cudaFuncAttributeMaxDynamicSharedMemorySize,
                         GEMM_SMEM_BYTES);

    float* c_xlr  = S + O_CXLR;
    float* c_h1   = S + O_CH1;
    float* c_xlr2 = S + O_CXLR2;
    float* c_h2   = S + O_CH2;
    float* comb   = S + O_COMB;
    float* faW    = S + O_FAW;
    float* wmean  = S + O_WM;
    float* Wc1    = S + O_WC1;
    float* Wc2    = S + O_WC2;
    float* Wb1    = S + O_WB1;
    float* Wb2    = S + O_WB2;
    float* b_xlr  = S + O_BXLR;
    float* b_h1   = S + O_BH1;
    float* b_h2   = S + O_BH2;
    float* xl3    = S + O_XL3;
    float* xr3    = S + O_XR3;
    int* bcnt = (int*)(S + O_BCNT);
    int* bel  = (int*)(S + O_BEL);
    int* ccnt = (int*)(S + O_CCNT);
    int* cel  = (int*)(S + O_CEL);

    // ---- Graph prep + weight prep ----
    izero<<<cdivll(NB, 256), 256>>>(bcnt, NB);
    izero<<<cdivll(NC, 256), 256>>>(ccnt, NC);
    build_lists<<<cdivll(EB, 256), 256>>>(bei, EB, bcnt, bel);
    build_lists<<<cdivll(EC, 256), 256>>>(cei, EC, ccnt, cel);
    concat2<<<cdivll(32 * 1024, 256), 256>>>(W[C1WL], W[C1WR], Wc1, 32, 512);
    concat2<<<cdivll(512 * 256, 256), 256>>>(W[C2WL], W[C2WR], Wc2, 512, 128);
    concat2<<<cdivll(192 * 1024, 256), 256>>>(W[B1WL], W[B1WR], Wb1, 192, 512);
    concat2<<<cdivll(512 * 256, 256), 256>>>(W[B2WL], W[B2WR], Wb2, 512, 128);
    transpose_faw1<<<cdivll(8 * 192 * 128, 256), 256>>>(W[FAW1], faW);
    fillk<<<cdivll((long long)NB * 2, 256), 256>>>(wmean, 0.0f, (long long)NB * 2);

    // ---- Community GNN ----
    gemm(cf, Wc1, c_xlr, nullptr, NC, 32, 1024, 0);
    gat_fused<32, 64, 8, true><<<cdivll((long long)NC * 8 * 32, 256), 256>>>(
        ccnt, cel, c_xlr, c_xlr + 512, 1024, W[C1ATT], W[C1B], c_h1, NC);

    gemm(c_h1, Wc2, c_xlr2, nullptr, NC, 512, 256, 0);
    gat_fused<16, 32, 4, true><<<cdivll((long long)NC * 4 * 16, 256), 256>>>(
        ccnt, cel, c_xlr2, c_xlr2 + 128, 256, W[C2ATT], W[C2B], c_h2, NC);

    // ---- Feature-attention fusion (head fused into GEMM epilogue) ----
    build_combined<<<cdivll((long long)NB * 192, 256), 256>>>(bf, c_h2, b2c, comb);
    gemm(comb, faW, nullptr, W[FAB1], NB, 192, 1024, 1, W[FAW2], W[FAB2], wmean);
    fuse_k<<<cdivll((long long)NB * 192, 256), 256>>>(comb, wmean);

    // ---- Building GNN ----
    gemm(comb, Wb1, b_xlr, nullptr, NB, 192, 1024, 0);
    gat_fused<32, 64, 8, true><<<cdivll((long long)NB * 8 * 32, 256), 256>>>(
        bcnt, bel, b_xlr, b_xlr + 512, 1024, W[B1ATT], W[B1B], b_h1, NB);

    gemm(b_h1, Wb2, b_xlr, nullptr, NB, 512, 256, 0);
    gat_fused<16, 32, 4, true><<<cdivll((long long)NB * 4 * 16, 256), 256>>>(
        bcnt, bel, b_xlr, b_xlr + 128, 256, W[B2ATT], W[B2B], b_h2, NB);

    small_xform<<<cdivll(NB, 256), 256>>>(b_h2, W[B3WL], W[B3WR], xl3, xr3, NB, 128);
    gat3_lsm<<<cdivll((long long)NB * 2, 256), 256>>>(
        bcnt, bel, xl3, xr3, W[B3ATT], W[B3B], (float*)d_out, NB);
}

// round 8
// speedup vs baseline: 5.5576x; 1.0475x over previous
#include <cuda_runtime.h>
#include <math.h>
#include <stdint.h>

// Problem constants
#define NB 100000
#define NC 10000
#define EB 400000
#define EC 80000
#define CAP 64

// ---------------------------------------------------------------------------
// Scratch layout (floats; int regions reinterpreted)
// ---------------------------------------------------------------------------
constexpr long long O_CXLR = 0;                                   // [NC,1024]
constexpr long long O_CH1  = O_CXLR + (long long)NC * 1024;       // [NC,512]
constexpr long long O_CXLR2= O_CH1  + (long long)NC * 512;        // [NC,256]
constexpr long long O_CH2  = O_CXLR2+ (long long)NC * 256;        // [NC,128]
constexpr long long O_FAW  = O_CH2  + (long long)NC * 128;        // [192,1024]
constexpr long long O_WM   = O_FAW  + (long long)192 * 1024;      // [NB,2]
constexpr long long O_WC1  = O_WM   + (long long)NB * 2;          // [32,1024]
constexpr long long O_WC2  = O_WC1  + (long long)32 * 1024;       // [512,256]
constexpr long long O_WB1  = O_WC2  + (long long)512 * 256;       // [192,1024]
constexpr long long O_WB2  = O_WB1  + (long long)192 * 1024;      // [512,256]
constexpr long long O_BXLR = O_WB2  + (long long)512 * 256;       // [NB,1024]
constexpr long long O_BH1  = O_BXLR + (long long)NB * 1024;       // [NB,512]
constexpr long long O_BH2  = O_BH1  + (long long)NB * 512;        // [NB,128]
constexpr long long O_XL3  = O_BH2  + (long long)NB * 128;        // [NB,2]
constexpr long long O_XR3  = O_XL3  + (long long)NB * 2;          // [NB,2]
constexpr long long O_BCNT = O_XR3  + (long long)NB * 2;          // int [NB]
constexpr long long O_BEL  = O_BCNT + (long long)NB;              // int [NB*CAP]
constexpr long long O_CCNT = O_BEL  + (long long)NB * CAP;        // int [NC]
constexpr long long O_CEL  = O_CCNT + (long long)NC;              // int [NC*CAP]
constexpr long long SCRATCH_TOTAL = O_CEL + (long long)NC * CAP;

__device__ float g_scratch[SCRATCH_TOTAL];

// ---------------------------------------------------------------------------
__global__ void fillk(float* __restrict__ x, float v, long long n) {
    long long i = (long long)blockIdx.x * blockDim.x + threadIdx.x;
    if (i < n) x[i] = v;
}

__global__ void izero(int* __restrict__ p, int n) {
    int i = blockIdx.x * blockDim.x + threadIdx.x;
    if (i < n) p[i] = 0;
}

// Bucket lists store SRC node ids directly.
__global__ void build_lists(const int* __restrict__ ei, int E,
                            int* __restrict__ cnt, int* __restrict__ el)
{
    int e = blockIdx.x * blockDim.x + threadIdx.x;
    if (e >= E) return;
    int s = ei[e];
    int d = ei[E + e];
    int slot = atomicAdd(&cnt[d], 1);
    if (slot < CAP) el[(long long)d * CAP + slot] = s;
}

// out[k][0..M-1] = a[k][...], out[k][M..2M-1] = b[k][...]
__global__ void concat2(const float* __restrict__ a, const float* __restrict__ b,
                        float* __restrict__ out, int K, int M)
{
    int i = blockIdx.x * blockDim.x + threadIdx.x;
    if (i >= K * 2 * M) return;
    int k = i / (2 * M), c = i % (2 * M);
    out[i] = (c < M) ? a[k * M + c] : b[k * M + (c - M)];
}

// fa_w1 (8,192,128) -> [192, 1024] with col = h*128 + j
__global__ void transpose_faw1(const float* __restrict__ w, float* __restrict__ out)
{
    int i = blockIdx.x * blockDim.x + threadIdx.x;
    if (i >= 8 * 192 * 128) return;
    int h = i / (192 * 128), r = (i / 128) % 192, j = i % 128;
    out[r * 1024 + h * 128 + j] = w[i];
}

// ---------------------------------------------------------------------------
// TF32 tensor-core GEMM, 3-stage cp.async pipeline, one barrier per k-tile.
// C[N,M] = A[N,K] @ B[K,M] (+bias, optional relu)
// 128x128x32 CTA tile, 8 warps, warp tile 64x32, mma.m16n8k8.tf32.
// MODE 0: plain A.  MODE 1: A = gather(bf|cx[map]), K=192.
// MODE 2: gather + per-row wmean scale (region k<64 vs k>=64).
// fa epilogue (w2 != null): per-head MLP head reduced in-register, softmax,
// atomicAdd 0.125*softmax into wmean. head = blockIdx.x.
// ---------------------------------------------------------------------------
#define AS_STRIDE 36
#define BS_STRIDE 132
#define ABUF (128 * AS_STRIDE)
#define BBUF (32 * BS_STRIDE)
#define BUFSZ (ABUF + BBUF)
#define STAGES 3
#define GEMM_SMEM_BYTES (STAGES * BUFSZ * 4)

__device__ __forceinline__ void cp16(uint32_t d, const void* s, bool pred) {
    int sz = pred ? 16 : 0;
    asm volatile("cp.async.ca.shared.global [%0], [%1], 16, %2;\n"
                 :: "r"(d), "l"(s), "r"(sz));
}

__device__ __forceinline__ void mma_tf32(float* c, unsigned a0, unsigned a1,
                                         unsigned a2, unsigned a3,
                                         unsigned b0, unsigned b1) {
    asm volatile(
        "mma.sync.aligned.m16n8k8.row.col.f32.tf32.tf32.f32 "
        "{%0,%1,%2,%3},{%4,%5,%6,%7},{%8,%9},{%0,%1,%2,%3};"
        : "+f"(c[0]), "+f"(c[1]), "+f"(c[2]), "+f"(c[3])
        : "r"(a0), "r"(a1), "r"(a2), "r"(a3), "r"(b0), "r"(b1));
}

template<int MODE>
__global__ void __launch_bounds__(256, 2) tf32gemm(
    const float* __restrict__ A, const float* __restrict__ B,
    float* __restrict__ C, const float* __restrict__ bias,
    int N, int K, int M, int relu,
    const float* __restrict__ w2, const float* __restrict__ b2,
    float* __restrict__ wmean,
    const float* __restrict__ gsrc0,   // bf  [N,64]   (MODE>=1)
    const float* __restrict__ gsrc1,   // cx  [NC,128] (MODE>=1)
    const int*   __restrict__ gmap,    // map [N]      (MODE>=1)
    const float* __restrict__ ascale)  // wmean [N,2]  (MODE==2)
{
    extern __shared__ float sm[];
    int tid = threadIdx.x;
    int warp = tid >> 5, lane = tid & 31;
    int wm = (warp >> 2) * 64;
    int wn = (warp & 3) * 32;
    int g  = lane >> 2;
    int tg = lane & 3;
    int rowBase = blockIdx.y * 128;
    int colBase = blockIdx.x * 128;

    uint32_t sbase = (uint32_t)__cvta_generic_to_shared(sm);

    float acc[4][4][4] = {};
    int T = K >> 5;

    // per-row wmean scales (MODE 2)
    float s0[8], s1[8];
    if (MODE == 2) {
        #pragma unroll
        for (int mi = 0; mi < 4; mi++) {
            #pragma unroll
            for (int hf = 0; hf < 2; hf++) {
                int gr = rowBase + wm + mi * 16 + g + hf * 8;
                int idx = mi * 2 + hf;
                if (gr < N) {
                    s0[idx] = ascale[(long long)gr * 2 + 0];
                    s1[idx] = ascale[(long long)gr * 2 + 1];
                } else { s0[idx] = 1.0f; s1[idx] = 1.0f; }
            }
        }
    }

    auto issue_tile = [&](int k0, int buf) {
        uint32_t abase = sbase + (uint32_t)(buf * BUFSZ) * 4u;
        uint32_t bbase = abase + (uint32_t)ABUF * 4u;
        #pragma unroll
        for (int it = 0; it < 4; it++) {
            int chunk = tid + it * 256;
            int r  = chunk >> 3;
            int kc = (chunk & 7) << 2;
            int gr = rowBase + r;
            bool pa = gr < N;
            const float* srcA;
            if (MODE == 0) {
                srcA = A + (long long)(pa ? gr : 0) * K + k0 + kc;
            } else {
                int k = k0 + kc;
                if (k < 64) {
                    srcA = gsrc0 + (long long)(pa ? gr : 0) * 64 + k;
                } else {
                    int m = pa ? gmap[gr] : 0;
                    srcA = gsrc1 + (long long)m * 128 + (k - 64);
                }
            }
            cp16(abase + (uint32_t)(r * AS_STRIDE + kc) * 4u, srcA, pa);
            int kk = chunk >> 5;
            int nn = (chunk & 31) << 2;
            const float* srcB = B + (long long)(k0 + kk) * M + colBase + nn;
            cp16(bbase + (uint32_t)(kk * BS_STRIDE + nn) * 4u, srcB, true);
        }
        asm volatile("cp.async.commit_group;\n");
    };

    issue_tile(0, 0);
    if (T > 1) issue_tile(32, 1);

    for (int t = 0; t < T; t++) {
        if (t + 1 < T) { asm volatile("cp.async.wait_group 1;\n"); }
        else           { asm volatile("cp.async.wait_group 0;\n"); }
        __syncthreads();
        if (t + 2 < T) issue_tile((t + 2) << 5, (t + 2) % STAGES);

        const float* as = sm + (t % STAGES) * BUFSZ;
        const float* bs = as + ABUF;
        bool reg1 = (MODE == 2) && ((t << 5) >= 64);

        #pragma unroll
        for (int ks = 0; ks < 32; ks += 8) {
            unsigned af[4][4], bf[4][2];
            #pragma unroll
            for (int mi = 0; mi < 4; mi++) {
                int m = wm + mi * 16 + g;
                float v0 = as[m * AS_STRIDE + ks + tg];
                float v1 = as[(m + 8) * AS_STRIDE + ks + tg];
                float v2 = as[m * AS_STRIDE + ks + tg + 4];
                float v3 = as[(m + 8) * AS_STRIDE + ks + tg + 4];
                if (MODE == 2) {
                    float sc0 = reg1 ? s1[mi * 2]     : s0[mi * 2];
                    float sc1 = reg1 ? s1[mi * 2 + 1] : s0[mi * 2 + 1];
                    v0 *= sc0; v1 *= sc1; v2 *= sc0; v3 *= sc1;
                }
                af[mi][0] = __float_as_uint(v0);
                af[mi][1] = __float_as_uint(v1);
                af[mi][2] = __float_as_uint(v2);
                af[mi][3] = __float_as_uint(v3);
            }
            #pragma unroll
            for (int nj = 0; nj < 4; nj++) {
                int n = wn + nj * 8 + g;
                bf[nj][0] = __float_as_uint(bs[(ks + tg) * BS_STRIDE + n]);
                bf[nj][1] = __float_as_uint(bs[(ks + tg + 4) * BS_STRIDE + n]);
            }
            #pragma unroll
            for (int mi = 0; mi < 4; mi++)
                #pragma unroll
                for (int nj = 0; nj < 4; nj++)
                    mma_tf32(acc[mi][nj], af[mi][0], af[mi][1], af[mi][2], af[mi][3],
                             bf[nj][0], bf[nj][1]);
        }
        // no trailing barrier: next-iter barrier precedes next issue
    }

    if (w2 == nullptr) {
        #pragma unroll
        for (int mi = 0; mi < 4; mi++) {
            #pragma unroll
            for (int nj = 0; nj < 4; nj++) {
                int row = rowBase + wm + mi * 16 + g;
                int col = colBase + wn + nj * 8 + tg * 2;
                float b0 = 0.f, b1 = 0.f;
                if (bias) { b0 = bias[col]; b1 = bias[col + 1]; }
                if (row < N) {
                    float2 v = make_float2(acc[mi][nj][0] + b0, acc[mi][nj][1] + b1);
                    if (relu) { v.x = fmaxf(v.x, 0.f); v.y = fmaxf(v.y, 0.f); }
                    *(float2*)(C + (long long)row * M + col) = v;
                }
                if (row + 8 < N) {
                    float2 v = make_float2(acc[mi][nj][2] + b0, acc[mi][nj][3] + b1);
                    if (relu) { v.x = fmaxf(v.x, 0.f); v.y = fmaxf(v.y, 0.f); }
                    *(float2*)(C + (long long)(row + 8) * M + col) = v;
                }
            }
        }
    } else {
        int h = blockIdx.x;
        float* srow = sm;
        __syncthreads();                    // all warps out of mainloop smem
        for (int i = tid; i < 256; i += 256) srow[i] = 0.0f;
        __syncthreads();

        #pragma unroll
        for (int mi = 0; mi < 4; mi++) {
            float p0a = 0.f, p1a = 0.f;
            float p0b = 0.f, p1b = 0.f;
            #pragma unroll
            for (int nj = 0; nj < 4; nj++) {
                int col_rel = wn + nj * 8 + tg * 2;
                float bb0 = bias[colBase + col_rel];
                float bb1 = bias[colBase + col_rel + 1];
                float2 wa = *(const float2*)(w2 + h * 256 + col_rel * 2);
                float2 wb = *(const float2*)(w2 + h * 256 + (col_rel + 1) * 2);
                float v0 = fmaxf(acc[mi][nj][0] + bb0, 0.f);
                float v1 = fmaxf(acc[mi][nj][1] + bb1, 0.f);
                p0a += v0 * wa.x + v1 * wb.x;
                p1a += v0 * wa.y + v1 * wb.y;
                float u0 = fmaxf(acc[mi][nj][2] + bb0, 0.f);
                float u1 = fmaxf(acc[mi][nj][3] + bb1, 0.f);
                p0b += u0 * wa.x + u1 * wb.x;
                p1b += u0 * wa.y + u1 * wb.y;
            }
            int ra = wm + mi * 16 + g;
            atomicAdd(&srow[ra * 2 + 0], p0a);
            atomicAdd(&srow[ra * 2 + 1], p1a);
            atomicAdd(&srow[(ra + 8) * 2 + 0], p0b);
            atomicAdd(&srow[(ra + 8) * 2 + 1], p1b);
        }
        __syncthreads();
        if (tid < 128) {
            int grow = rowBase + tid;
            if (grow < N) {
                float sa = srow[tid * 2 + 0] + b2[h * 2 + 0];
                float sb = srow[tid * 2 + 1] + b2[h * 2 + 1];
                float mx = fmaxf(sa, sb);
                float e0 = expf(sa - mx), e1 = expf(sb - mx);
                float inv = 0.125f / (e0 + e1);
                atomicAdd(&wmean[(long long)grow * 2 + 0], e0 * inv);
                atomicAdd(&wmean[(long long)grow * 2 + 1], e1 * inv);
            }
        }
    }
}

// ---------------------------------------------------------------------------
// Fused GATv2 softmax+aggregate, online softmax, float4 per lane.
// One LPG-lane group per (dst, head); D == 4*LPG.
// ---------------------------------------------------------------------------
template<int LPG, int D, int H, bool RELU>
__global__ void gat_fused(const int* __restrict__ cnt, const int* __restrict__ el,
                          const float* __restrict__ xl, const float* __restrict__ xr,
                          int ldx,
                          const float* __restrict__ att, const float* __restrict__ bias,
                          float* __restrict__ out, int Nnodes)
{
    static_assert(D == 4 * LPG, "");
    long long t = (long long)blockIdx.x * blockDim.x + threadIdx.x;
    long long gidx = t / LPG;
    int lane = (int)(t % LPG);
    if (gidx >= (long long)Nnodes * H) return;
    int dst = (int)(gidx / H), h = (int)(gidx % H);

    float4 xr4 = *(const float4*)(xr + (long long)dst * ldx + h * D + lane * 4);
    float4 a4  = *(const float4*)(att + (long long)h * D + lane * 4);

    int c = cnt[dst]; if (c > CAP) c = CAP;
    const int* lst = el + (long long)dst * CAP;

    float mx = -1e30f, wsum = 0.0f;
    float4 acc = make_float4(0.f, 0.f, 0.f, 0.f);

    for (int i = 0; i <= c; i++) {
        int src = (i == c) ? dst : lst[i];
        float4 v = *(const float4*)(xl + (long long)src * ldx + h * D + lane * 4);
        float e0 = v.x + xr4.x; e0 = e0 > 0.f ? e0 : 0.2f * e0;
        float e1 = v.y + xr4.y; e1 = e1 > 0.f ? e1 : 0.2f * e1;
        float e2 = v.z + xr4.z; e2 = e2 > 0.f ? e2 : 0.2f * e2;
        float e3 = v.w + xr4.w; e3 = e3 > 0.f ? e3 : 0.2f * e3;
        float s = e0 * a4.x + e1 * a4.y + e2 * a4.z + e3 * a4.w;
        #pragma unroll
        for (int o = LPG / 2; o; o >>= 1) s += __shfl_xor_sync(0xffffffffu, s, o, LPG);
        if (s > mx) {
            float f = expf(mx - s);
            wsum *= f;
            acc.x *= f; acc.y *= f; acc.z *= f; acc.w *= f;
            mx = s;
        }
        float p = expf(s - mx);
        wsum += p;
        acc.x += p * v.x; acc.y += p * v.y; acc.z += p * v.z; acc.w += p * v.w;
    }

    float inv = 1.0f / wsum;
    const float* pb = bias + h * D + lane * 4;
    float4 o4;
    o4.x = acc.x * inv + pb[0];
    o4.y = acc.y * inv + pb[1];
    o4.z = acc.z * inv + pb[2];
    o4.w = acc.w * inv + pb[3];
    if (RELU) {
        o4.x = fmaxf(o4.x, 0.f); o4.y = fmaxf(o4.y, 0.f);
        o4.z = fmaxf(o4.z, 0.f); o4.w = fmaxf(o4.w, 0.f);
    }
    *(float4*)(out + ((long long)dst * H + h) * D + lane * 4) = o4;
}

// Layer 3 (H=1, D=2) fused with final log-softmax, writes d_out.
__global__ void gat3_lsm(const int* __restrict__ cnt, const int* __restrict__ el,
                         const float* __restrict__ xl, const float* __restrict__ xr,
                         const float* __restrict__ att, const float* __restrict__ bias,
                         float* __restrict__ out, int Nnodes)
{
    long long t = (long long)blockIdx.x * blockDim.x + threadIdx.x;
    long long gidx = t >> 1;
    int lane = (int)(t & 1);
    if (gidx >= Nnodes) return;
    int dst = (int)gidx;

    float xr_d = xr[(long long)dst * 2 + lane];
    float a_d  = att[lane];
    int c = cnt[dst]; if (c > CAP) c = CAP;
    const int* lst = el + (long long)dst * CAP;

    float mx = -1e30f, wsum = 0.0f, acc = 0.0f;
    for (int i = 0; i <= c; i++) {
        int src = (i == c) ? dst : lst[i];
        float xv = xl[(long long)src * 2 + lane];
        float v = xv + xr_d;
        v = v > 0.0f ? v : 0.2f * v;
        float s = v * a_d;
        s += __shfl_xor_sync(0xffffffffu, s, 1, 2);
        if (s > mx) {
            float f = expf(mx - s);
            wsum *= f; acc *= f; mx = s;
        }
        float p = expf(s - mx);
        wsum += p;
        acc += p * xv;
    }
    float v = acc / wsum + bias[lane];
    float o = __shfl_xor_sync(0xffffffffu, v, 1, 2);
    float m2 = fmaxf(v, o);
    float lse = m2 + logf(expf(v - m2) + expf(o - m2));
    out[(long long)dst * 2 + lane] = v - lse;
}

// ---------------------------------------------------------------------------
__global__ void small_xform(const float* __restrict__ x, const float* __restrict__ wl,
                            const float* __restrict__ wr, float* __restrict__ xl,
                            float* __restrict__ xr, int N, int K)
{
    int n = blockIdx.x * blockDim.x + threadIdx.x;
    if (n >= N) return;
    float a0 = 0, a1 = 0, b0 = 0, b1 = 0;
    const float* px = x + (long long)n * K;
    for (int k = 0; k < K; k++) {
        float v = px[k];
        a0 += v * wl[k * 2]; a1 += v * wl[k * 2 + 1];
        b0 += v * wr[k * 2]; b1 += v * wr[k * 2 + 1];
    }
    xl[n * 2] = a0; xl[n * 2 + 1] = a1;
    xr[n * 2] = b0; xr[n * 2 + 1] = b1;
}

// ---------------------------------------------------------------------------
static inline int cdivll(long long a, long long b) { return (int)((a + b - 1) / b); }

static void gemm0(const float* A, const float* B, float* C, const float* bias,
                  int N, int K, int M, int relu)
{
    dim3 grid(M / 128, (N + 127) / 128);
    tf32gemm<0><<<grid, 256, GEMM_SMEM_BYTES>>>(A, B, C, bias, N, K, M, relu,
        nullptr, nullptr, nullptr, nullptr, nullptr, nullptr, nullptr);
}

extern "C" void kernel_launch(void* const* d_in, const int* in_sizes, int n_in,
                              void* d_out, int out_size)
{
    int idx_bf = 0, idx_cf = 1, idx_bei, idx_cei, idx_map, base_w;
    if (in_sizes[2] == 2 * EB) { idx_bei = 2; idx_cei = 3; idx_map = 4; base_w = 5; }
    else                       { base_w = 2; idx_bei = 26; idx_cei = 27; idx_map = 28; }
    const float* bf  = (const float*)d_in[idx_bf];
    const float* cf  = (const float*)d_in[idx_cf];
    const int*   bei = (const int*)d_in[idx_bei];
    const int*   cei = (const int*)d_in[idx_cei];
    const int*   b2c = (const int*)d_in[idx_map];

    enum { C1WL, C1WR, C1ATT, C1B, C2WL, C2WR, C2ATT, C2B,
           FAW1, FAB1, FAW2, FAB2,
           B1WL, B1WR, B1ATT, B1B, B2WL, B2WR, B2ATT, B2B,
           B3WL, B3WR, B3ATT, B3B };
    const float* W[24];
    for (int i = 0; i < 24; i++) W[i] = (const float*)d_in[base_w + i];

    float* S;
    cudaGetSymbolAddress((void**)&S, g_scratch);
    cudaFuncSetAttribute(tf32gemm<0>, cudaFuncAttributeMaxDynamicSharedMemorySize, GEMM_SMEM_BYTES);
    cudaFuncSetAttribute(tf32gemm<1>, cudaFuncAttributeMaxDynamicSharedMemorySize, GEMM_SMEM_BYTES);
    cudaFuncSetAttribute(tf32gemm<2>, cudaFuncAttributeMaxDynamicSharedMemorySize, GEMM_SMEM_BYTES);

    float* c_xlr  = S + O_CXLR;
    float* c_h1   = S + O_CH1;
    float* c_xlr2 = S + O_CXLR2;
    float* c_h2   = S + O_CH2;
    float* faW    = S + O_FAW;
    float* wmean  = S + O_WM;
    float* Wc1    = S + O_WC1;
    float* Wc2    = S + O_WC2;
    float* Wb1    = S + O_WB1;
    float* Wb2    = S + O_WB2;
    float* b_xlr  = S + O_BXLR;
    float* b_h1   = S + O_BH1;
    float* b_h2   = S + O_BH2;
    float* xl3    = S + O_XL3;
    float* xr3    = S + O_XR3;
    int* bcnt = (int*)(S + O_BCNT);
    int* bel  = (int*)(S + O_BEL);
    int* ccnt = (int*)(S + O_CCNT);
    int* cel  = (int*)(S + O_CEL);

    // ---- Community prep + GNN (ordered so ncu window hits gemm/gat) ----
    concat2<<<cdivll(32 * 1024, 256), 256>>>(W[C1WL], W[C1WR], Wc1, 32, 512);      // 1
    izero<<<cdivll(NC, 256), 256>>>(ccnt, NC);                                      // 2
    build_lists<<<cdivll(EC, 256), 256>>>(cei, EC, ccnt, cel);                      // 3
    gemm0(cf, Wc1, c_xlr, nullptr, NC, 32, 1024, 0);                                // 4
    gat_fused<16, 64, 8, true><<<cdivll((long long)NC * 8 * 16, 256), 256>>>(      // 5
        ccnt, cel, c_xlr, c_xlr + 512, 1024, W[C1ATT], W[C1B], c_h1, NC);

    concat2<<<cdivll(512 * 256, 256), 256>>>(W[C2WL], W[C2WR], Wc2, 512, 128);
    gemm0(c_h1, Wc2, c_xlr2, nullptr, NC, 512, 256, 0);
    gat_fused<8, 32, 4, true><<<cdivll((long long)NC * 4 * 8, 256), 256>>>(
        ccnt, cel, c_xlr2, c_xlr2 + 128, 256, W[C2ATT], W[C2B], c_h2, NC);

    // ---- Feature-attention (A gathered in-GEMM; head fused in epilogue) ----
    transpose_faw1<<<cdivll(8 * 192 * 128, 256), 256>>>(W[FAW1], faW);
    fillk<<<cdivll((long long)NB * 2, 256), 256>>>(wmean, 0.0f, (long long)NB * 2);
    izero<<<cdivll(NB, 256), 256>>>(bcnt, NB);
    build_lists<<<cdivll(EB, 256), 256>>>(bei, EB, bcnt, bel);
    {
        dim3 grid(1024 / 128, (NB + 127) / 128);
        tf32gemm<1><<<grid, 256, GEMM_SMEM_BYTES>>>(
            nullptr, faW, nullptr, W[FAB1], NB, 192, 1024, 1,
            W[FAW2], W[FAB2], wmean, bf, c_h2, b2c, nullptr);
    }

    // ---- Building GNN (b1 A = gather * wmean, fused into GEMM) ----
    concat2<<<cdivll(192 * 1024, 256), 256>>>(W[B1WL], W[B1WR], Wb1, 192, 512);
    {
        dim3 grid(1024 / 128, (NB + 127) / 128);
        tf32gemm<2><<<grid, 256, GEMM_SMEM_BYTES>>>(
            nullptr, Wb1, b_xlr, nullptr, NB, 192, 1024, 0,
            nullptr, nullptr, nullptr, bf, c_h2, b2c, wmean);
    }
    gat_fused<16, 64, 8, true><<<cdivll((long long)NB * 8 * 16, 256), 256>>>(
        bcnt, bel, b_xlr, b_xlr + 512, 1024, W[B1ATT], W[B1B], b_h1, NB);

    concat2<<<cdivll(512 * 256, 256), 256>>>(W[B2WL], W[B2WR], Wb2, 512, 128);
    gemm0(b_h1, Wb2, b_xlr, nullptr, NB, 512, 256, 0);
    gat_fused<8, 32, 4, true><<<cdivll((long long)NB * 4 * 8, 256), 256>>>(
        bcnt, bel, b_xlr, b_xlr + 128, 256, W[B2ATT], W[B2B], b_h2, NB);

    small_xform<<<cdivll(NB, 256), 256>>>(b_h2, W[B3WL], W[B3WR], xl3, xr3, NB, 128);
    gat3_lsm<<<cdivll((long long)NB * 2, 256), 256>>>(
        bcnt, bel, xl3, xr3, W[B3ATT], W[B3B], (float*)d_out, NB);
}